// round 6
// baseline (speedup 1.0000x reference)
#include <cuda_runtime.h>
#include <cuda_bf16.h>

#define NN 50000
#define NE 800000
#define D  128
#define NG 128

#define SA 132   // pool-staging row stride (floats)
#define SW 136   // bf16 row stride for A tiles

// ---------------- device scratch ----------------
__device__ float g_hA[NN * D];
__device__ float g_hB[NN * D];
__device__ int   g_beg[NN];
__device__ int   g_pos[NN];
__device__ int   g_cnt[NN];
__device__ int   g_col[NE];
__device__ int   g_total;
// fragment-ordered weights: [layer][gemm][cb(16)][kk(8)][lane(32)] = {bh0,bh1,bl0,bl1}
__device__ uint4 g_wfrag[3][2][16][8][32];

#define SCAN_B 98
#define WFRAG_N (6 * 16 * 8 * 32)   // 24576

// split float2 -> bf16x2 hi (ret) + bf16x2 lo (out)
__device__ __forceinline__ unsigned sp2(float2 x, unsigned& lo) {
    __nv_bfloat162 h = __float22bfloat162_rn(x);
    unsigned hu = *reinterpret_cast<unsigned*>(&h);
    float hx = __uint_as_float(hu << 16);
    float hy = __uint_as_float(hu & 0xffff0000u);
    __nv_bfloat162 l = __float22bfloat162_rn(make_float2(x.x - hx, x.y - hy));
    lo = *reinterpret_cast<unsigned*>(&l);
    return hu;
}

// ---------------- init: wfrag pack + zero cnt/out/total (one launch) ----------------
__global__ void k_init(const float* __restrict__ W10, const float* __restrict__ W20,
                       const float* __restrict__ W11, const float* __restrict__ W21,
                       const float* __restrict__ W12, const float* __restrict__ W22,
                       float* __restrict__ out) {
    int i = blockIdx.x * 256 + threadIdx.x;
    if (i < WFRAG_N) {
        int which = i >> 12;            // 6 weights x 4096 frags
        int rem   = i & 4095;
        int cb    = rem >> 8;           // 16 col-groups
        int kk    = (rem >> 5) & 7;     // 8 k-steps
        int lane  = rem & 31;
        int grp = lane >> 2, qid = lane & 3;
        const float* W = (which == 0) ? W10 : (which == 1) ? W20 : (which == 2) ? W11
                        : (which == 3) ? W21 : (which == 4) ? W12 : W22;
        int layer = which >> 1, g = which & 1;
        int n  = cb * 8 + grp;
        int k0 = kk * 16 + 2 * qid;
        float x0 = __ldg(&W[(k0)     * 128 + n]);
        float x1 = __ldg(&W[(k0 + 1) * 128 + n]);
        float x2 = __ldg(&W[(k0 + 8) * 128 + n]);
        float x3 = __ldg(&W[(k0 + 9) * 128 + n]);
        unsigned bl0, bl1;
        unsigned bh0 = sp2(make_float2(x0, x1), bl0);
        unsigned bh1 = sp2(make_float2(x2, x3), bl1);
        g_wfrag[layer][g][cb][kk][lane] = make_uint4(bh0, bh1, bl0, bl1);
    } else if (i < WFRAG_N + NN) {
        g_cnt[i - WFRAG_N] = 0;
    } else if (i < WFRAG_N + NN + NG * D) {
        out[i - WFRAG_N - NN] = 0.f;
    } else if (i == WFRAG_N + NN + NG * D) {
        g_total = 0;
    }
}

// ---------------- CSR build ----------------
__global__ void k_count(const int* __restrict__ dst) {
    int e = blockIdx.x * blockDim.x + threadIdx.x;
    if (e < NE) atomicAdd(&g_cnt[dst[e]], 1);
}

// single-pass: block scan + atomic block base (segment order is irrelevant)
__global__ void k_assign() {
    int t = threadIdx.x, b = blockIdx.x;
    int i = b * 512 + t;
    int v = (i < NN) ? g_cnt[i] : 0;
    int x = v;
    #pragma unroll
    for (int o = 1; o < 32; o <<= 1) {
        int y = __shfl_up_sync(0xffffffffu, x, o);
        if ((t & 31) >= o) x += y;
    }
    __shared__ int ws[16];
    __shared__ int sbase;
    if ((t & 31) == 31) ws[t >> 5] = x;
    __syncthreads();
    if (t < 16) {
        int y = ws[t];
        #pragma unroll
        for (int o = 1; o < 16; o <<= 1) {
            int z = __shfl_up_sync(0xffffu, y, o);
            if (t >= o) y += z;
        }
        ws[t] = y;
    }
    __syncthreads();
    int off = (t >= 32) ? ws[(t >> 5) - 1] : 0;
    int incl = x + off;
    if (t == 511) sbase = atomicAdd(&g_total, incl);
    __syncthreads();
    if (i < NN) {
        int p = sbase + incl - v;
        g_beg[i] = p;
        g_pos[i] = p;
    }
}

__global__ void k_scatter(const int* __restrict__ src, const int* __restrict__ dst) {
    int e = blockIdx.x * blockDim.x + threadIdx.x;
    if (e < NE) {
        int d = dst[e];
        int p = atomicAdd(&g_pos[d], 1);
        g_col[p] = src[e];
    }
}

// ---------------- fused layer ----------------
#define A_BYTES (2 * 64 * SW * 2)   // Ah+Al bf16 = 34816 B (pool fp32 [64][SA]=33792 fits)
#define LAYER_SMEM A_BYTES

__device__ __forceinline__ void mma_bf16(float* c, const unsigned* a, const unsigned* b) {
    asm volatile("mma.sync.aligned.m16n8k16.row.col.f32.bf16.bf16.f32 "
        "{%0,%1,%2,%3}, {%4,%5,%6,%7}, {%8,%9}, {%0,%1,%2,%3};"
        : "+f"(c[0]), "+f"(c[1]), "+f"(c[2]), "+f"(c[3])
        : "r"(a[0]), "r"(a[1]), "r"(a[2]), "r"(a[3]), "r"(b[0]), "r"(b[1]));
}

// L2-only load (avoid polluting L1, which holds W fragments)
__device__ __forceinline__ float4 ldcg4(const float4* p) {
    float4 v;
    asm volatile("ld.global.cg.v4.f32 {%0,%1,%2,%3}, [%4];"
                 : "=f"(v.x), "=f"(v.y), "=f"(v.z), "=f"(v.w) : "l"(p));
    return v;
}

__global__ void __launch_bounds__(512, 4)
k_layer(const float* __restrict__ hin, const float* __restrict__ eps, int layer,
        const float* __restrict__ B1, const float* __restrict__ B2,
        float* __restrict__ hout,
        const int* __restrict__ gid, float* __restrict__ out) {
    extern __shared__ float sm[];
    __nv_bfloat16* Ah = (__nv_bfloat16*)sm;          // [64][SW]
    __nv_bfloat16* Al = Ah + 64 * SW;
    float* Ps = sm;                                  // pool staging union [64][SA]
    __shared__ int s_row;

    const int t    = threadIdx.x;
    const int wid  = t >> 5;
    const int lane = t & 31;
    const int wm   = wid & 1;      // rows wm*32..+31
    const int wn   = wid >> 1;     // cols wn*16..+15
    const int grp  = lane >> 2;
    const int qid  = lane & 3;
    const int row0 = blockIdx.x * 64;

    if (t == 0) s_row = 16;
    float ev = 1.0f + __ldg(&eps[layer]);
    __syncthreads();

    // ---- gather z (dynamic row stealing), split to bf16 hi/lo tiles ----
    {
        const float4* hv = (const float4*)hin;
        int r = wid;                       // first 16 rows static
        while (r < 64) {
            int node = row0 + r;
            float4 a = make_float4(0.f, 0.f, 0.f, 0.f);
            if (node < NN) {
                a = ldcg4(&hv[node * 32 + lane]);
                a.x *= ev; a.y *= ev; a.z *= ev; a.w *= ev;
                int jb = g_beg[node];
                int je = jb + g_cnt[node];
                int j = jb;
                for (; j + 4 <= je; j += 4) {
                    int s0 = g_col[j], s1 = g_col[j + 1], s2 = g_col[j + 2], s3 = g_col[j + 3];
                    float4 x0 = ldcg4(&hv[s0 * 32 + lane]);
                    float4 x1 = ldcg4(&hv[s1 * 32 + lane]);
                    float4 x2 = ldcg4(&hv[s2 * 32 + lane]);
                    float4 x3 = ldcg4(&hv[s3 * 32 + lane]);
                    a.x += x0.x + x1.x + x2.x + x3.x;
                    a.y += x0.y + x1.y + x2.y + x3.y;
                    a.z += x0.z + x1.z + x2.z + x3.z;
                    a.w += x0.w + x1.w + x2.w + x3.w;
                }
                for (; j < je; j++) {
                    int s = g_col[j];
                    float4 x = ldcg4(&hv[s * 32 + lane]);
                    a.x += x.x; a.y += x.y; a.z += x.z; a.w += x.w;
                }
            }
            unsigned l0, l1;
            unsigned h0 = sp2(make_float2(a.x, a.y), l0);
            unsigned h1 = sp2(make_float2(a.z, a.w), l1);
            *(uint2*)&Ah[r * SW + lane * 4] = make_uint2(h0, h1);
            *(uint2*)&Al[r * SW + lane * 4] = make_uint2(l0, l1);
            if (lane == 0) r = atomicAdd(&s_row, 1);
            r = __shfl_sync(0xffffffffu, r, 0);
        }
    }
    __syncthreads();

    float acc[2][2][4];
    #pragma unroll
    for (int mt = 0; mt < 2; mt++)
        #pragma unroll
        for (int nt = 0; nt < 2; nt++)
            #pragma unroll
            for (int q = 0; q < 4; q++) acc[mt][nt][q] = 0.f;

    // ---- GEMM 1: LDS A-frags + LDG.128 W-frags (L1-resident) + HMMA ----
    #pragma unroll 2
    for (int kk = 0; kk < 8; kk++) {
        int k0 = kk * 16;
        unsigned ah[2][4], al[2][4];
        #pragma unroll
        for (int mt = 0; mt < 2; mt++) {
            const __nv_bfloat16* ap = &Ah[(wm * 32 + mt * 16 + grp) * SW + k0 + 2 * qid];
            const __nv_bfloat16* aq = &Al[(wm * 32 + mt * 16 + grp) * SW + k0 + 2 * qid];
            ah[mt][0] = *(const unsigned*)ap;
            ah[mt][1] = *(const unsigned*)(ap + 8 * SW);
            ah[mt][2] = *(const unsigned*)(ap + 8);
            ah[mt][3] = *(const unsigned*)(ap + 8 * SW + 8);
            al[mt][0] = *(const unsigned*)aq;
            al[mt][1] = *(const unsigned*)(aq + 8 * SW);
            al[mt][2] = *(const unsigned*)(aq + 8);
            al[mt][3] = *(const unsigned*)(aq + 8 * SW + 8);
        }
        #pragma unroll
        for (int nt = 0; nt < 2; nt++) {
            uint4 f = __ldg(&g_wfrag[layer][0][wn * 2 + nt][kk][lane]);
            unsigned bh[2] = {f.x, f.y};
            unsigned bl[2] = {f.z, f.w};
            #pragma unroll
            for (int mt = 0; mt < 2; mt++) {
                mma_bf16(acc[mt][nt], ah[mt], bh);
                mma_bf16(acc[mt][nt], al[mt], bh);
                mma_bf16(acc[mt][nt], ah[mt], bl);
            }
        }
    }

    __syncthreads();

    // ---- epilogue 1: relu + split -> Ah/Al ----
    #pragma unroll
    for (int mt = 0; mt < 2; mt++) {
        int r0 = wm * 32 + mt * 16 + grp;
        #pragma unroll
        for (int nt = 0; nt < 2; nt++) {
            int c = wn * 16 + nt * 8 + qid * 2;
            float b0 = __ldg(&B1[c]);
            float b1v = __ldg(&B1[c + 1]);
            float2 v0 = make_float2(fmaxf(acc[mt][nt][0] + b0, 0.f), fmaxf(acc[mt][nt][1] + b1v, 0.f));
            float2 v1 = make_float2(fmaxf(acc[mt][nt][2] + b0, 0.f), fmaxf(acc[mt][nt][3] + b1v, 0.f));
            unsigned l0, l1;
            unsigned h0 = sp2(v0, l0);
            unsigned h1 = sp2(v1, l1);
            *(unsigned*)&Ah[r0 * SW + c] = h0;
            *(unsigned*)&Al[r0 * SW + c] = l0;
            *(unsigned*)&Ah[(r0 + 8) * SW + c] = h1;
            *(unsigned*)&Al[(r0 + 8) * SW + c] = l1;
        }
    }
    __syncthreads();

    #pragma unroll
    for (int mt = 0; mt < 2; mt++)
        #pragma unroll
        for (int nt = 0; nt < 2; nt++)
            #pragma unroll
            for (int q = 0; q < 4; q++) acc[mt][nt][q] = 0.f;

    // ---- GEMM 2 ----
    #pragma unroll 2
    for (int kk = 0; kk < 8; kk++) {
        int k0 = kk * 16;
        unsigned ah[2][4], al[2][4];
        #pragma unroll
        for (int mt = 0; mt < 2; mt++) {
            const __nv_bfloat16* ap = &Ah[(wm * 32 + mt * 16 + grp) * SW + k0 + 2 * qid];
            const __nv_bfloat16* aq = &Al[(wm * 32 + mt * 16 + grp) * SW + k0 + 2 * qid];
            ah[mt][0] = *(const unsigned*)ap;
            ah[mt][1] = *(const unsigned*)(ap + 8 * SW);
            ah[mt][2] = *(const unsigned*)(ap + 8);
            ah[mt][3] = *(const unsigned*)(ap + 8 * SW + 8);
            al[mt][0] = *(const unsigned*)aq;
            al[mt][1] = *(const unsigned*)(aq + 8 * SW);
            al[mt][2] = *(const unsigned*)(aq + 8);
            al[mt][3] = *(const unsigned*)(aq + 8 * SW + 8);
        }
        #pragma unroll
        for (int nt = 0; nt < 2; nt++) {
            uint4 f = __ldg(&g_wfrag[layer][1][wn * 2 + nt][kk][lane]);
            unsigned bh[2] = {f.x, f.y};
            unsigned bl[2] = {f.z, f.w};
            #pragma unroll
            for (int mt = 0; mt < 2; mt++) {
                mma_bf16(acc[mt][nt], ah[mt], bh);
                mma_bf16(acc[mt][nt], al[mt], bh);
                mma_bf16(acc[mt][nt], ah[mt], bl);
            }
        }
    }

    // ---- epilogue 2 ----
    if (hout) {
        #pragma unroll
        for (int mt = 0; mt < 2; mt++) {
            int r0 = row0 + wm * 32 + mt * 16 + grp;
            #pragma unroll
            for (int nt = 0; nt < 2; nt++) {
                int c = wn * 16 + nt * 8 + qid * 2;
                float b0 = __ldg(&B2[c]);
                float b1v = __ldg(&B2[c + 1]);
                if (r0 < NN)
                    *(float2*)&hout[r0 * 128 + c] =
                        make_float2(acc[mt][nt][0] + b0, acc[mt][nt][1] + b1v);
                if (r0 + 8 < NN)
                    *(float2*)&hout[(r0 + 8) * 128 + c] =
                        make_float2(acc[mt][nt][2] + b0, acc[mt][nt][3] + b1v);
            }
        }
    } else {
        __syncthreads();   // Ah/Al no longer needed; reuse as fp32 pool staging
        #pragma unroll
        for (int mt = 0; mt < 2; mt++) {
            int r0 = wm * 32 + mt * 16 + grp;
            #pragma unroll
            for (int nt = 0; nt < 2; nt++) {
                int c = wn * 16 + nt * 8 + qid * 2;
                float b0 = __ldg(&B2[c]);
                float b1v = __ldg(&B2[c + 1]);
                *(float2*)&Ps[r0 * SA + c] =
                    make_float2(acc[mt][nt][0] + b0, acc[mt][nt][1] + b1v);
                *(float2*)&Ps[(r0 + 8) * SA + c] =
                    make_float2(acc[mt][nt][2] + b0, acc[mt][nt][3] + b1v);
            }
        }
        __syncthreads();
        int gg = t >> 7;
        int c  = t & 127;
        float pacc = 0.f;
        int cur = -1;
        for (int r = gg * 16; r < gg * 16 + 16; r++) {
            int node = row0 + r;
            if (node >= NN) break;
            int g = __ldg(&gid[node]);
            if (g != cur) {
                if (cur >= 0) atomicAdd(&out[cur * 128 + c], pacc);
                cur = g;
                pacc = 0.f;
            }
            pacc += Ps[r * SA + c];
        }
        if (cur >= 0) atomicAdd(&out[cur * 128 + c], pacc);
    }
}

// ---------------- launch ----------------
extern "C" void kernel_launch(void* const* d_in, const int* in_sizes, int n_in,
                              void* d_out, int out_size) {
    const float* feats = (const float*)d_in[0];
    const int*   esrc  = (const int*)d_in[1];
    const int*   edst  = (const int*)d_in[2];
    const int*   gid   = (const int*)d_in[3];
    const float* eps   = (const float*)d_in[4];
    const float* W1[3] = {(const float*)d_in[5],  (const float*)d_in[9],  (const float*)d_in[13]};
    const float* B1[3] = {(const float*)d_in[6],  (const float*)d_in[10], (const float*)d_in[14]};
    const float* W2[3] = {(const float*)d_in[7],  (const float*)d_in[11], (const float*)d_in[15]};
    const float* B2[3] = {(const float*)d_in[8],  (const float*)d_in[12], (const float*)d_in[16]};
    float* out = (float*)d_out;
    (void)in_sizes; (void)n_in; (void)out_size;

    cudaFuncSetAttribute(k_layer, cudaFuncAttributeMaxDynamicSharedMemorySize, LAYER_SMEM);

    float* hA; cudaGetSymbolAddress((void**)&hA, g_hA);
    float* hB; cudaGetSymbolAddress((void**)&hB, g_hB);

    int initN = WFRAG_N + NN + NG * D + 1;
    k_init<<<(initN + 255) / 256, 256>>>(W1[0], W2[0], W1[1], W2[1], W1[2], W2[2], out);

    k_count<<<(NE + 255) / 256, 256>>>(edst);
    k_assign<<<SCAN_B, 512>>>();
    k_scatter<<<(NE + 255) / 256, 256>>>(esrc, edst);

    int grid = (NN + 63) / 64;
    k_layer<<<grid, 512, LAYER_SMEM>>>(feats, eps, 0, B1[0], B2[0], hA, gid, out);
    k_layer<<<grid, 512, LAYER_SMEM>>>(hA,    eps, 1, B1[1], B2[1], hB, gid, out);
    k_layer<<<grid, 512, LAYER_SMEM>>>(hB,    eps, 2, B1[2], B2[2], nullptr, gid, out);
}

// round 8
// speedup vs baseline: 2.6761x; 2.6761x over previous
#include <cuda_runtime.h>
#include <cuda_bf16.h>

#define NN 50000
#define NE 800000
#define D  128
#define NG 128

#define SA 132   // pool-staging row stride (floats)
#define SW 136   // bf16 row stride for A tiles

// ---------------- device scratch ----------------
__device__ float g_hA[NN * D];
__device__ float g_hB[NN * D];
__device__ int   g_beg[NN];
__device__ int   g_pos[NN];
__device__ int   g_cnt[NN];
__device__ int   g_col[NE];
__device__ int   g_total;
// fragment-ordered weights: [layer][gemm][cb(16)][kk(8)][lane(32)] = {bh0,bh1,bl0,bl1}
__device__ uint4 g_wfrag[3][2][16][8][32];

#define SCAN_B 98
#define WFRAG_N (6 * 16 * 8 * 32)   // 24576

// split float2 -> bf16x2 hi (ret) + bf16x2 lo (out)
__device__ __forceinline__ unsigned sp2(float2 x, unsigned& lo) {
    __nv_bfloat162 h = __float22bfloat162_rn(x);
    unsigned hu = *reinterpret_cast<unsigned*>(&h);
    float hx = __uint_as_float(hu << 16);
    float hy = __uint_as_float(hu & 0xffff0000u);
    __nv_bfloat162 l = __float22bfloat162_rn(make_float2(x.x - hx, x.y - hy));
    lo = *reinterpret_cast<unsigned*>(&l);
    return hu;
}

// ---------------- init: wfrag pack + zero cnt/out/total (one launch) ----------------
__global__ void k_init(const float* __restrict__ W10, const float* __restrict__ W20,
                       const float* __restrict__ W11, const float* __restrict__ W21,
                       const float* __restrict__ W12, const float* __restrict__ W22,
                       float* __restrict__ out) {
    int i = blockIdx.x * 256 + threadIdx.x;
    if (i < WFRAG_N) {
        int which = i >> 12;            // 6 weights x 4096 frags
        int rem   = i & 4095;
        int cb    = rem >> 8;           // 16 col-groups
        int kk    = (rem >> 5) & 7;     // 8 k-steps
        int lane  = rem & 31;
        int grp = lane >> 2, qid = lane & 3;
        const float* W = (which == 0) ? W10 : (which == 1) ? W20 : (which == 2) ? W11
                        : (which == 3) ? W21 : (which == 4) ? W12 : W22;
        int layer = which >> 1, g = which & 1;
        int n  = cb * 8 + grp;
        int k0 = kk * 16 + 2 * qid;
        float x0 = __ldg(&W[(k0)     * 128 + n]);
        float x1 = __ldg(&W[(k0 + 1) * 128 + n]);
        float x2 = __ldg(&W[(k0 + 8) * 128 + n]);
        float x3 = __ldg(&W[(k0 + 9) * 128 + n]);
        unsigned bl0, bl1;
        unsigned bh0 = sp2(make_float2(x0, x1), bl0);
        unsigned bh1 = sp2(make_float2(x2, x3), bl1);
        g_wfrag[layer][g][cb][kk][lane] = make_uint4(bh0, bh1, bl0, bl1);
    } else if (i < WFRAG_N + NN) {
        g_cnt[i - WFRAG_N] = 0;
    } else if (i < WFRAG_N + NN + NG * D) {
        out[i - WFRAG_N - NN] = 0.f;
    } else if (i == WFRAG_N + NN + NG * D) {
        g_total = 0;
    }
}

// ---------------- CSR build ----------------
__global__ void k_count(const int* __restrict__ dst) {
    int e = blockIdx.x * blockDim.x + threadIdx.x;
    if (e < NE) atomicAdd(&g_cnt[dst[e]], 1);
}

// single-pass: block scan + atomic block base (segment order is irrelevant)
__global__ void k_assign() {
    int t = threadIdx.x, b = blockIdx.x;
    int i = b * 512 + t;
    int v = (i < NN) ? g_cnt[i] : 0;
    int x = v;
    #pragma unroll
    for (int o = 1; o < 32; o <<= 1) {
        int y = __shfl_up_sync(0xffffffffu, x, o);
        if ((t & 31) >= o) x += y;
    }
    __shared__ int ws[16];
    __shared__ int sbase;
    if ((t & 31) == 31) ws[t >> 5] = x;
    __syncthreads();
    if (t < 16) {
        int y = ws[t];
        #pragma unroll
        for (int o = 1; o < 16; o <<= 1) {
            int z = __shfl_up_sync(0xffffu, y, o);
            if (t >= o) y += z;
        }
        ws[t] = y;
    }
    __syncthreads();
    int off = (t >= 32) ? ws[(t >> 5) - 1] : 0;
    int incl = x + off;
    if (t == 511) sbase = atomicAdd(&g_total, incl);
    __syncthreads();
    if (i < NN) {
        int p = sbase + incl - v;
        g_beg[i] = p;
        g_pos[i] = p;
    }
}

__global__ void k_scatter(const int* __restrict__ src, const int* __restrict__ dst) {
    int e = blockIdx.x * blockDim.x + threadIdx.x;
    if (e < NE) {
        int d = dst[e];
        int p = atomicAdd(&g_pos[d], 1);
        g_col[p] = src[e];
    }
}

// ---------------- fused layer ----------------
#define A_BYTES (2 * 64 * SW * 2)   // Ah+Al bf16 = 34816 B (pool fp32 [64][SA]=33792 fits)
#define LAYER_SMEM A_BYTES

__device__ __forceinline__ void mma_bf16(float* c, const unsigned* a, const unsigned* b) {
    asm volatile("mma.sync.aligned.m16n8k16.row.col.f32.bf16.bf16.f32 "
        "{%0,%1,%2,%3}, {%4,%5,%6,%7}, {%8,%9}, {%0,%1,%2,%3};"
        : "+f"(c[0]), "+f"(c[1]), "+f"(c[2]), "+f"(c[3])
        : "r"(a[0]), "r"(a[1]), "r"(a[2]), "r"(a[3]), "r"(b[0]), "r"(b[1]));
}

// L2-only load (avoid polluting L1, which holds W fragments)
__device__ __forceinline__ float4 ldcg4(const float4* p) {
    float4 v;
    asm volatile("ld.global.cg.v4.f32 {%0,%1,%2,%3}, [%4];"
                 : "=f"(v.x), "=f"(v.y), "=f"(v.z), "=f"(v.w) : "l"(p));
    return v;
}

__global__ void __launch_bounds__(512, 2)   // 64 regs/thread — NO spills (R6 lesson)
k_layer(const float* __restrict__ hin, const float* __restrict__ eps, int layer,
        const float* __restrict__ B1, const float* __restrict__ B2,
        float* __restrict__ hout,
        const int* __restrict__ gid, float* __restrict__ out) {
    extern __shared__ float sm[];
    __nv_bfloat16* Ah = (__nv_bfloat16*)sm;          // [64][SW]
    __nv_bfloat16* Al = Ah + 64 * SW;
    float* Ps = sm;                                  // pool staging union [64][SA]
    __shared__ int s_row;

    const int t    = threadIdx.x;
    const int wid  = t >> 5;
    const int lane = t & 31;
    const int wm   = wid & 1;      // rows wm*32..+31
    const int wn   = wid >> 1;     // cols wn*16..+15
    const int grp  = lane >> 2;
    const int qid  = lane & 3;
    const int row0 = blockIdx.x * 64;

    if (t == 0) s_row = 16;
    float ev = 1.0f + __ldg(&eps[layer]);
    __syncthreads();

    // ---- gather z (dynamic row stealing), split to bf16 hi/lo tiles ----
    {
        const float4* hv = (const float4*)hin;
        int r = wid;                       // first 16 rows static
        while (r < 64) {
            int node = row0 + r;
            float4 a = make_float4(0.f, 0.f, 0.f, 0.f);
            if (node < NN) {
                a = ldcg4(&hv[node * 32 + lane]);
                a.x *= ev; a.y *= ev; a.z *= ev; a.w *= ev;
                int jb = g_beg[node];
                int je = jb + g_cnt[node];
                int j = jb;
                for (; j + 4 <= je; j += 4) {
                    int s0 = g_col[j], s1 = g_col[j + 1], s2 = g_col[j + 2], s3 = g_col[j + 3];
                    float4 x0 = ldcg4(&hv[s0 * 32 + lane]);
                    float4 x1 = ldcg4(&hv[s1 * 32 + lane]);
                    float4 x2 = ldcg4(&hv[s2 * 32 + lane]);
                    float4 x3 = ldcg4(&hv[s3 * 32 + lane]);
                    a.x += x0.x + x1.x + x2.x + x3.x;
                    a.y += x0.y + x1.y + x2.y + x3.y;
                    a.z += x0.z + x1.z + x2.z + x3.z;
                    a.w += x0.w + x1.w + x2.w + x3.w;
                }
                for (; j < je; j++) {
                    int s = g_col[j];
                    float4 x = ldcg4(&hv[s * 32 + lane]);
                    a.x += x.x; a.y += x.y; a.z += x.z; a.w += x.w;
                }
            }
            unsigned l0, l1;
            unsigned h0 = sp2(make_float2(a.x, a.y), l0);
            unsigned h1 = sp2(make_float2(a.z, a.w), l1);
            *(uint2*)&Ah[r * SW + lane * 4] = make_uint2(h0, h1);
            *(uint2*)&Al[r * SW + lane * 4] = make_uint2(l0, l1);
            if (lane == 0) r = atomicAdd(&s_row, 1);
            r = __shfl_sync(0xffffffffu, r, 0);
        }
    }
    __syncthreads();

    float acc[2][2][4];
    #pragma unroll
    for (int mt = 0; mt < 2; mt++)
        #pragma unroll
        for (int nt = 0; nt < 2; nt++)
            #pragma unroll
            for (int q = 0; q < 4; q++) acc[mt][nt][q] = 0.f;

    // ---- GEMM 1: LDS A-frags + LDG.128 W-frags (L1-resident) + HMMA ----
    #pragma unroll 2
    for (int kk = 0; kk < 8; kk++) {
        int k0 = kk * 16;
        unsigned ah[2][4], al[2][4];
        #pragma unroll
        for (int mt = 0; mt < 2; mt++) {
            const __nv_bfloat16* ap = &Ah[(wm * 32 + mt * 16 + grp) * SW + k0 + 2 * qid];
            const __nv_bfloat16* aq = &Al[(wm * 32 + mt * 16 + grp) * SW + k0 + 2 * qid];
            ah[mt][0] = *(const unsigned*)ap;
            ah[mt][1] = *(const unsigned*)(ap + 8 * SW);
            ah[mt][2] = *(const unsigned*)(ap + 8);
            ah[mt][3] = *(const unsigned*)(ap + 8 * SW + 8);
            al[mt][0] = *(const unsigned*)aq;
            al[mt][1] = *(const unsigned*)(aq + 8 * SW);
            al[mt][2] = *(const unsigned*)(aq + 8);
            al[mt][3] = *(const unsigned*)(aq + 8 * SW + 8);
        }
        #pragma unroll
        for (int nt = 0; nt < 2; nt++) {
            uint4 f = __ldg(&g_wfrag[layer][0][wn * 2 + nt][kk][lane]);
            unsigned bh[2] = {f.x, f.y};
            unsigned bl[2] = {f.z, f.w};
            #pragma unroll
            for (int mt = 0; mt < 2; mt++) {
                mma_bf16(acc[mt][nt], ah[mt], bh);
                mma_bf16(acc[mt][nt], al[mt], bh);
                mma_bf16(acc[mt][nt], ah[mt], bl);
            }
        }
    }

    __syncthreads();

    // ---- epilogue 1: relu + split -> Ah/Al ----
    #pragma unroll
    for (int mt = 0; mt < 2; mt++) {
        int r0 = wm * 32 + mt * 16 + grp;
        #pragma unroll
        for (int nt = 0; nt < 2; nt++) {
            int c = wn * 16 + nt * 8 + qid * 2;
            float b0 = __ldg(&B1[c]);
            float b1v = __ldg(&B1[c + 1]);
            float2 v0 = make_float2(fmaxf(acc[mt][nt][0] + b0, 0.f), fmaxf(acc[mt][nt][1] + b1v, 0.f));
            float2 v1 = make_float2(fmaxf(acc[mt][nt][2] + b0, 0.f), fmaxf(acc[mt][nt][3] + b1v, 0.f));
            unsigned l0, l1;
            unsigned h0 = sp2(v0, l0);
            unsigned h1 = sp2(v1, l1);
            *(unsigned*)&Ah[r0 * SW + c] = h0;
            *(unsigned*)&Al[r0 * SW + c] = l0;
            *(unsigned*)&Ah[(r0 + 8) * SW + c] = h1;
            *(unsigned*)&Al[(r0 + 8) * SW + c] = l1;
        }
    }
    __syncthreads();

    #pragma unroll
    for (int mt = 0; mt < 2; mt++)
        #pragma unroll
        for (int nt = 0; nt < 2; nt++)
            #pragma unroll
            for (int q = 0; q < 4; q++) acc[mt][nt][q] = 0.f;

    // ---- GEMM 2 ----
    #pragma unroll 2
    for (int kk = 0; kk < 8; kk++) {
        int k0 = kk * 16;
        unsigned ah[2][4], al[2][4];
        #pragma unroll
        for (int mt = 0; mt < 2; mt++) {
            const __nv_bfloat16* ap = &Ah[(wm * 32 + mt * 16 + grp) * SW + k0 + 2 * qid];
            const __nv_bfloat16* aq = &Al[(wm * 32 + mt * 16 + grp) * SW + k0 + 2 * qid];
            ah[mt][0] = *(const unsigned*)ap;
            ah[mt][1] = *(const unsigned*)(ap + 8 * SW);
            ah[mt][2] = *(const unsigned*)(ap + 8);
            ah[mt][3] = *(const unsigned*)(ap + 8 * SW + 8);
            al[mt][0] = *(const unsigned*)aq;
            al[mt][1] = *(const unsigned*)(aq + 8 * SW);
            al[mt][2] = *(const unsigned*)(aq + 8);
            al[mt][3] = *(const unsigned*)(aq + 8 * SW + 8);
        }
        #pragma unroll
        for (int nt = 0; nt < 2; nt++) {
            uint4 f = __ldg(&g_wfrag[layer][1][wn * 2 + nt][kk][lane]);
            unsigned bh[2] = {f.x, f.y};
            unsigned bl[2] = {f.z, f.w};
            #pragma unroll
            for (int mt = 0; mt < 2; mt++) {
                mma_bf16(acc[mt][nt], ah[mt], bh);
                mma_bf16(acc[mt][nt], al[mt], bh);
                mma_bf16(acc[mt][nt], ah[mt], bl);
            }
        }
    }

    // ---- epilogue 2 ----
    if (hout) {
        #pragma unroll
        for (int mt = 0; mt < 2; mt++) {
            int r0 = row0 + wm * 32 + mt * 16 + grp;
            #pragma unroll
            for (int nt = 0; nt < 2; nt++) {
                int c = wn * 16 + nt * 8 + qid * 2;
                float b0 = __ldg(&B2[c]);
                float b1v = __ldg(&B2[c + 1]);
                if (r0 < NN)
                    *(float2*)&hout[r0 * 128 + c] =
                        make_float2(acc[mt][nt][0] + b0, acc[mt][nt][1] + b1v);
                if (r0 + 8 < NN)
                    *(float2*)&hout[(r0 + 8) * 128 + c] =
                        make_float2(acc[mt][nt][2] + b0, acc[mt][nt][3] + b1v);
            }
        }
    } else {
        __syncthreads();   // Ah/Al no longer needed; reuse as fp32 pool staging
        #pragma unroll
        for (int mt = 0; mt < 2; mt++) {
            int r0 = wm * 32 + mt * 16 + grp;
            #pragma unroll
            for (int nt = 0; nt < 2; nt++) {
                int c = wn * 16 + nt * 8 + qid * 2;
                float b0 = __ldg(&B2[c]);
                float b1v = __ldg(&B2[c + 1]);
                *(float2*)&Ps[r0 * SA + c] =
                    make_float2(acc[mt][nt][0] + b0, acc[mt][nt][1] + b1v);
                *(float2*)&Ps[(r0 + 8) * SA + c] =
                    make_float2(acc[mt][nt][2] + b0, acc[mt][nt][3] + b1v);
            }
        }
        __syncthreads();
        int gg = t >> 7;
        int c  = t & 127;
        float pacc = 0.f;
        int cur = -1;
        for (int r = gg * 16; r < gg * 16 + 16; r++) {
            int node = row0 + r;
            if (node >= NN) break;
            int g = __ldg(&gid[node]);
            if (g != cur) {
                if (cur >= 0) atomicAdd(&out[cur * 128 + c], pacc);
                cur = g;
                pacc = 0.f;
            }
            pacc += Ps[r * SA + c];
        }
        if (cur >= 0) atomicAdd(&out[cur * 128 + c], pacc);
    }
}

// ---------------- launch ----------------
extern "C" void kernel_launch(void* const* d_in, const int* in_sizes, int n_in,
                              void* d_out, int out_size) {
    const float* feats = (const float*)d_in[0];
    const int*   esrc  = (const int*)d_in[1];
    const int*   edst  = (const int*)d_in[2];
    const int*   gid   = (const int*)d_in[3];
    const float* eps   = (const float*)d_in[4];
    const float* W1[3] = {(const float*)d_in[5],  (const float*)d_in[9],  (const float*)d_in[13]};
    const float* B1[3] = {(const float*)d_in[6],  (const float*)d_in[10], (const float*)d_in[14]};
    const float* W2[3] = {(const float*)d_in[7],  (const float*)d_in[11], (const float*)d_in[15]};
    const float* B2[3] = {(const float*)d_in[8],  (const float*)d_in[12], (const float*)d_in[16]};
    float* out = (float*)d_out;
    (void)in_sizes; (void)n_in; (void)out_size;

    cudaFuncSetAttribute(k_layer, cudaFuncAttributeMaxDynamicSharedMemorySize, LAYER_SMEM);

    float* hA; cudaGetSymbolAddress((void**)&hA, g_hA);
    float* hB; cudaGetSymbolAddress((void**)&hB, g_hB);

    int initN = WFRAG_N + NN + NG * D + 1;
    k_init<<<(initN + 255) / 256, 256>>>(W1[0], W2[0], W1[1], W2[1], W1[2], W2[2], out);

    k_count<<<(NE + 255) / 256, 256>>>(edst);
    k_assign<<<SCAN_B, 512>>>();
    k_scatter<<<(NE + 255) / 256, 256>>>(esrc, edst);

    int grid = (NN + 63) / 64;
    k_layer<<<grid, 512, LAYER_SMEM>>>(feats, eps, 0, B1[0], B2[0], hA, gid, out);
    k_layer<<<grid, 512, LAYER_SMEM>>>(hA,    eps, 1, B1[1], B2[1], hB, gid, out);
    k_layer<<<grid, 512, LAYER_SMEM>>>(hB,    eps, 2, B1[2], B2[2], nullptr, gid, out);
}

// round 9
// speedup vs baseline: 2.8616x; 1.0693x over previous
#include <cuda_runtime.h>
#include <cuda_bf16.h>

#define NN 50000
#define NE 800000
#define D  128
#define NG 128

#define SA 132   // pool-staging row stride (floats)
#define SW 136   // bf16 row stride for A tiles
#define TM 32    // tile rows per block

// ---------------- device scratch ----------------
__device__ float g_hA[NN * D];
__device__ float g_hB[NN * D];
__device__ int   g_beg[NN];
__device__ int   g_pos[NN];
__device__ int   g_cnt[NN];
__device__ int   g_col[NE];
__device__ int   g_total;
// fragment-ordered weights: [layer][gemm][cb(16)][kk(8)][lane(32)] = {bh0,bh1,bl0,bl1}
__device__ uint4 g_wfrag[3][2][16][8][32];

#define SCAN_B 98
#define WFRAG_N (6 * 16 * 8 * 32)   // 24576

// split float2 -> bf16x2 hi (ret) + bf16x2 lo (out)
__device__ __forceinline__ unsigned sp2(float2 x, unsigned& lo) {
    __nv_bfloat162 h = __float22bfloat162_rn(x);
    unsigned hu = *reinterpret_cast<unsigned*>(&h);
    float hx = __uint_as_float(hu << 16);
    float hy = __uint_as_float(hu & 0xffff0000u);
    __nv_bfloat162 l = __float22bfloat162_rn(make_float2(x.x - hx, x.y - hy));
    lo = *reinterpret_cast<unsigned*>(&l);
    return hu;
}

// ---------------- init: wfrag pack + zero cnt/out/total (one launch) ----------------
__global__ void k_init(const float* __restrict__ W10, const float* __restrict__ W20,
                       const float* __restrict__ W11, const float* __restrict__ W21,
                       const float* __restrict__ W12, const float* __restrict__ W22,
                       float* __restrict__ out) {
    int i = blockIdx.x * 256 + threadIdx.x;
    if (i < WFRAG_N) {
        int which = i >> 12;            // 6 weights x 4096 frags
        int rem   = i & 4095;
        int cb    = rem >> 8;           // 16 col-groups
        int kk    = (rem >> 5) & 7;     // 8 k-steps
        int lane  = rem & 31;
        int grp = lane >> 2, qid = lane & 3;
        const float* W = (which == 0) ? W10 : (which == 1) ? W20 : (which == 2) ? W11
                        : (which == 3) ? W21 : (which == 4) ? W12 : W22;
        int layer = which >> 1, g = which & 1;
        int n  = cb * 8 + grp;
        int k0 = kk * 16 + 2 * qid;
        float x0 = __ldg(&W[(k0)     * 128 + n]);
        float x1 = __ldg(&W[(k0 + 1) * 128 + n]);
        float x2 = __ldg(&W[(k0 + 8) * 128 + n]);
        float x3 = __ldg(&W[(k0 + 9) * 128 + n]);
        unsigned bl0, bl1;
        unsigned bh0 = sp2(make_float2(x0, x1), bl0);
        unsigned bh1 = sp2(make_float2(x2, x3), bl1);
        g_wfrag[layer][g][cb][kk][lane] = make_uint4(bh0, bh1, bl0, bl1);
    } else if (i < WFRAG_N + NN) {
        g_cnt[i - WFRAG_N] = 0;
    } else if (i < WFRAG_N + NN + NG * D) {
        out[i - WFRAG_N - NN] = 0.f;
    } else if (i == WFRAG_N + NN + NG * D) {
        g_total = 0;
    }
}

// ---------------- CSR build ----------------
__global__ void k_count(const int* __restrict__ dst) {
    int e4 = blockIdx.x * blockDim.x + threadIdx.x;
    if (e4 * 4 < NE) {
        int4 d = __ldg((const int4*)dst + e4);
        atomicAdd(&g_cnt[d.x], 1);
        atomicAdd(&g_cnt[d.y], 1);
        atomicAdd(&g_cnt[d.z], 1);
        atomicAdd(&g_cnt[d.w], 1);
    }
}

// single-pass: block scan + atomic block base (segment order is irrelevant)
__global__ void k_assign() {
    int t = threadIdx.x, b = blockIdx.x;
    int i = b * 512 + t;
    int v = (i < NN) ? g_cnt[i] : 0;
    int x = v;
    #pragma unroll
    for (int o = 1; o < 32; o <<= 1) {
        int y = __shfl_up_sync(0xffffffffu, x, o);
        if ((t & 31) >= o) x += y;
    }
    __shared__ int ws[16];
    __shared__ int sbase;
    if ((t & 31) == 31) ws[t >> 5] = x;
    __syncthreads();
    if (t < 16) {
        int y = ws[t];
        #pragma unroll
        for (int o = 1; o < 16; o <<= 1) {
            int z = __shfl_up_sync(0xffffu, y, o);
            if (t >= o) y += z;
        }
        ws[t] = y;
    }
    __syncthreads();
    int off = (t >= 32) ? ws[(t >> 5) - 1] : 0;
    int incl = x + off;
    if (t == 511) sbase = atomicAdd(&g_total, incl);
    __syncthreads();
    if (i < NN) {
        int p = sbase + incl - v;
        g_beg[i] = p;
        g_pos[i] = p;
    }
}

__global__ void k_scatter(const int* __restrict__ src, const int* __restrict__ dst) {
    int e4 = blockIdx.x * blockDim.x + threadIdx.x;
    if (e4 * 4 < NE) {
        int4 d = __ldg((const int4*)dst + e4);
        int4 s = __ldg((const int4*)src + e4);
        g_col[atomicAdd(&g_pos[d.x], 1)] = s.x;
        g_col[atomicAdd(&g_pos[d.y], 1)] = s.y;
        g_col[atomicAdd(&g_pos[d.z], 1)] = s.z;
        g_col[atomicAdd(&g_pos[d.w], 1)] = s.w;
    }
}

// ---------------- fused layer ----------------
#define A_BYTES (2 * TM * SW * 2)   // Ah+Al bf16 = 17408 B (pool fp32 [32][SA]=16896 fits)
#define LAYER_SMEM A_BYTES

__device__ __forceinline__ void mma_bf16(float* c, const unsigned* a, const unsigned* b) {
    asm volatile("mma.sync.aligned.m16n8k16.row.col.f32.bf16.bf16.f32 "
        "{%0,%1,%2,%3}, {%4,%5,%6,%7}, {%8,%9}, {%0,%1,%2,%3};"
        : "+f"(c[0]), "+f"(c[1]), "+f"(c[2]), "+f"(c[3])
        : "r"(a[0]), "r"(a[1]), "r"(a[2]), "r"(a[3]), "r"(b[0]), "r"(b[1]));
}

// L2-only load (avoid polluting L1, which holds W fragments)
__device__ __forceinline__ float4 ldcg4(const float4* p) {
    float4 v;
    asm volatile("ld.global.cg.v4.f32 {%0,%1,%2,%3}, [%4];"
                 : "=f"(v.x), "=f"(v.y), "=f"(v.z), "=f"(v.w) : "l"(p));
    return v;
}

__global__ void __launch_bounds__(256, 4)   // 64 regs/thread — NO spills (R6 lesson)
k_layer(const float* __restrict__ hin, const float* __restrict__ eps, int layer,
        const float* __restrict__ B1, const float* __restrict__ B2,
        float* __restrict__ hout,
        const int* __restrict__ gid, float* __restrict__ out) {
    extern __shared__ float sm[];
    __nv_bfloat16* Ah = (__nv_bfloat16*)sm;          // [TM][SW]
    __nv_bfloat16* Al = Ah + TM * SW;
    float* Ps = sm;                                  // pool staging union [TM][SA]
    __shared__ int s_row;

    const int t    = threadIdx.x;
    const int wid  = t >> 5;       // 0..7
    const int lane = t & 31;
    const int wn   = wid;          // cols wn*16..+15, rows 0..31 (all warps)
    const int grp  = lane >> 2;
    const int qid  = lane & 3;
    const int row0 = blockIdx.x * TM;

    if (t == 0) s_row = 8;
    float ev = 1.0f + __ldg(&eps[layer]);
    __syncthreads();

    // ---- gather z (dynamic row stealing), split to bf16 hi/lo tiles ----
    {
        const float4* hv = (const float4*)hin;
        int r = wid;                       // first 8 rows static
        while (r < TM) {
            int node = row0 + r;
            float4 a = make_float4(0.f, 0.f, 0.f, 0.f);
            if (node < NN) {
                a = ldcg4(&hv[node * 32 + lane]);
                a.x *= ev; a.y *= ev; a.z *= ev; a.w *= ev;
                int jb = g_beg[node];
                int je = jb + g_cnt[node];
                int j = jb;
                for (; j + 4 <= je; j += 4) {
                    int s0 = g_col[j], s1 = g_col[j + 1], s2 = g_col[j + 2], s3 = g_col[j + 3];
                    float4 x0 = ldcg4(&hv[s0 * 32 + lane]);
                    float4 x1 = ldcg4(&hv[s1 * 32 + lane]);
                    float4 x2 = ldcg4(&hv[s2 * 32 + lane]);
                    float4 x3 = ldcg4(&hv[s3 * 32 + lane]);
                    a.x += x0.x + x1.x + x2.x + x3.x;
                    a.y += x0.y + x1.y + x2.y + x3.y;
                    a.z += x0.z + x1.z + x2.z + x3.z;
                    a.w += x0.w + x1.w + x2.w + x3.w;
                }
                for (; j < je; j++) {
                    int s = g_col[j];
                    float4 x = ldcg4(&hv[s * 32 + lane]);
                    a.x += x.x; a.y += x.y; a.z += x.z; a.w += x.w;
                }
            }
            unsigned l0, l1;
            unsigned h0 = sp2(make_float2(a.x, a.y), l0);
            unsigned h1 = sp2(make_float2(a.z, a.w), l1);
            *(uint2*)&Ah[r * SW + lane * 4] = make_uint2(h0, h1);
            *(uint2*)&Al[r * SW + lane * 4] = make_uint2(l0, l1);
            if (lane == 0) r = atomicAdd(&s_row, 1);
            r = __shfl_sync(0xffffffffu, r, 0);
        }
    }
    __syncthreads();

    float acc[2][2][4];
    #pragma unroll
    for (int mt = 0; mt < 2; mt++)
        #pragma unroll
        for (int nt = 0; nt < 2; nt++)
            #pragma unroll
            for (int q = 0; q < 4; q++) acc[mt][nt][q] = 0.f;

    // ---- GEMM 1: LDS A-frags + LDG.128 W-frags (L1-resident) + HMMA ----
    #pragma unroll 2
    for (int kk = 0; kk < 8; kk++) {
        int k0 = kk * 16;
        unsigned ah[2][4], al[2][4];
        #pragma unroll
        for (int mt = 0; mt < 2; mt++) {
            const __nv_bfloat16* ap = &Ah[(mt * 16 + grp) * SW + k0 + 2 * qid];
            const __nv_bfloat16* aq = &Al[(mt * 16 + grp) * SW + k0 + 2 * qid];
            ah[mt][0] = *(const unsigned*)ap;
            ah[mt][1] = *(const unsigned*)(ap + 8 * SW);
            ah[mt][2] = *(const unsigned*)(ap + 8);
            ah[mt][3] = *(const unsigned*)(ap + 8 * SW + 8);
            al[mt][0] = *(const unsigned*)aq;
            al[mt][1] = *(const unsigned*)(aq + 8 * SW);
            al[mt][2] = *(const unsigned*)(aq + 8);
            al[mt][3] = *(const unsigned*)(aq + 8 * SW + 8);
        }
        #pragma unroll
        for (int nt = 0; nt < 2; nt++) {
            uint4 f = __ldg(&g_wfrag[layer][0][wn * 2 + nt][kk][lane]);
            unsigned bh[2] = {f.x, f.y};
            unsigned bl[2] = {f.z, f.w};
            #pragma unroll
            for (int mt = 0; mt < 2; mt++) {
                mma_bf16(acc[mt][nt], ah[mt], bh);
                mma_bf16(acc[mt][nt], al[mt], bh);
                mma_bf16(acc[mt][nt], ah[mt], bl);
            }
        }
    }

    __syncthreads();

    // ---- epilogue 1: relu + split -> Ah/Al ----
    #pragma unroll
    for (int mt = 0; mt < 2; mt++) {
        int r0 = mt * 16 + grp;
        #pragma unroll
        for (int nt = 0; nt < 2; nt++) {
            int c = wn * 16 + nt * 8 + qid * 2;
            float b0 = __ldg(&B1[c]);
            float b1v = __ldg(&B1[c + 1]);
            float2 v0 = make_float2(fmaxf(acc[mt][nt][0] + b0, 0.f), fmaxf(acc[mt][nt][1] + b1v, 0.f));
            float2 v1 = make_float2(fmaxf(acc[mt][nt][2] + b0, 0.f), fmaxf(acc[mt][nt][3] + b1v, 0.f));
            unsigned l0, l1;
            unsigned h0 = sp2(v0, l0);
            unsigned h1 = sp2(v1, l1);
            *(unsigned*)&Ah[r0 * SW + c] = h0;
            *(unsigned*)&Al[r0 * SW + c] = l0;
            *(unsigned*)&Ah[(r0 + 8) * SW + c] = h1;
            *(unsigned*)&Al[(r0 + 8) * SW + c] = l1;
        }
    }
    __syncthreads();

    #pragma unroll
    for (int mt = 0; mt < 2; mt++)
        #pragma unroll
        for (int nt = 0; nt < 2; nt++)
            #pragma unroll
            for (int q = 0; q < 4; q++) acc[mt][nt][q] = 0.f;

    // ---- GEMM 2 ----
    #pragma unroll 2
    for (int kk = 0; kk < 8; kk++) {
        int k0 = kk * 16;
        unsigned ah[2][4], al[2][4];
        #pragma unroll
        for (int mt = 0; mt < 2; mt++) {
            const __nv_bfloat16* ap = &Ah[(mt * 16 + grp) * SW + k0 + 2 * qid];
            const __nv_bfloat16* aq = &Al[(mt * 16 + grp) * SW + k0 + 2 * qid];
            ah[mt][0] = *(const unsigned*)ap;
            ah[mt][1] = *(const unsigned*)(ap + 8 * SW);
            ah[mt][2] = *(const unsigned*)(ap + 8);
            ah[mt][3] = *(const unsigned*)(ap + 8 * SW + 8);
            al[mt][0] = *(const unsigned*)aq;
            al[mt][1] = *(const unsigned*)(aq + 8 * SW);
            al[mt][2] = *(const unsigned*)(aq + 8);
            al[mt][3] = *(const unsigned*)(aq + 8 * SW + 8);
        }
        #pragma unroll
        for (int nt = 0; nt < 2; nt++) {
            uint4 f = __ldg(&g_wfrag[layer][1][wn * 2 + nt][kk][lane]);
            unsigned bh[2] = {f.x, f.y};
            unsigned bl[2] = {f.z, f.w};
            #pragma unroll
            for (int mt = 0; mt < 2; mt++) {
                mma_bf16(acc[mt][nt], ah[mt], bh);
                mma_bf16(acc[mt][nt], al[mt], bh);
                mma_bf16(acc[mt][nt], ah[mt], bl);
            }
        }
    }

    // ---- epilogue 2 ----
    if (hout) {
        #pragma unroll
        for (int mt = 0; mt < 2; mt++) {
            int r0 = row0 + mt * 16 + grp;
            #pragma unroll
            for (int nt = 0; nt < 2; nt++) {
                int c = wn * 16 + nt * 8 + qid * 2;
                float b0 = __ldg(&B2[c]);
                float b1v = __ldg(&B2[c + 1]);
                if (r0 < NN)
                    *(float2*)&hout[r0 * 128 + c] =
                        make_float2(acc[mt][nt][0] + b0, acc[mt][nt][1] + b1v);
                if (r0 + 8 < NN)
                    *(float2*)&hout[(r0 + 8) * 128 + c] =
                        make_float2(acc[mt][nt][2] + b0, acc[mt][nt][3] + b1v);
            }
        }
    } else {
        __syncthreads();   // Ah/Al no longer needed; reuse as fp32 pool staging
        #pragma unroll
        for (int mt = 0; mt < 2; mt++) {
            int r0 = mt * 16 + grp;
            #pragma unroll
            for (int nt = 0; nt < 2; nt++) {
                int c = wn * 16 + nt * 8 + qid * 2;
                float b0 = __ldg(&B2[c]);
                float b1v = __ldg(&B2[c + 1]);
                *(float2*)&Ps[r0 * SA + c] =
                    make_float2(acc[mt][nt][0] + b0, acc[mt][nt][1] + b1v);
                *(float2*)&Ps[(r0 + 8) * SA + c] =
                    make_float2(acc[mt][nt][2] + b0, acc[mt][nt][3] + b1v);
            }
        }
        __syncthreads();
        int gg = t >> 7;       // 2 groups of 16 rows
        int c  = t & 127;
        float pacc = 0.f;
        int cur = -1;
        for (int r = gg * 16; r < gg * 16 + 16; r++) {
            int node = row0 + r;
            if (node >= NN) break;
            int g = __ldg(&gid[node]);
            if (g != cur) {
                if (cur >= 0) atomicAdd(&out[cur * 128 + c], pacc);
                cur = g;
                pacc = 0.f;
            }
            pacc += Ps[r * SA + c];
        }
        if (cur >= 0) atomicAdd(&out[cur * 128 + c], pacc);
    }
}

// ---------------- launch ----------------
extern "C" void kernel_launch(void* const* d_in, const int* in_sizes, int n_in,
                              void* d_out, int out_size) {
    const float* feats = (const float*)d_in[0];
    const int*   esrc  = (const int*)d_in[1];
    const int*   edst  = (const int*)d_in[2];
    const int*   gid   = (const int*)d_in[3];
    const float* eps   = (const float*)d_in[4];
    const float* W1[3] = {(const float*)d_in[5],  (const float*)d_in[9],  (const float*)d_in[13]};
    const float* B1[3] = {(const float*)d_in[6],  (const float*)d_in[10], (const float*)d_in[14]};
    const float* W2[3] = {(const float*)d_in[7],  (const float*)d_in[11], (const float*)d_in[15]};
    const float* B2[3] = {(const float*)d_in[8],  (const float*)d_in[12], (const float*)d_in[16]};
    float* out = (float*)d_out;
    (void)in_sizes; (void)n_in; (void)out_size;

    cudaFuncSetAttribute(k_layer, cudaFuncAttributeMaxDynamicSharedMemorySize, LAYER_SMEM);

    float* hA; cudaGetSymbolAddress((void**)&hA, g_hA);
    float* hB; cudaGetSymbolAddress((void**)&hB, g_hB);

    int initN = WFRAG_N + NN + NG * D + 1;
    k_init<<<(initN + 255) / 256, 256>>>(W1[0], W2[0], W1[1], W2[1], W1[2], W2[2], out);

    k_count<<<(NE / 4 + 255) / 256, 256>>>(edst);
    k_assign<<<SCAN_B, 512>>>();
    k_scatter<<<(NE / 4 + 255) / 256, 256>>>(esrc, edst);

    int grid = (NN + TM - 1) / TM;
    k_layer<<<grid, 256, LAYER_SMEM>>>(feats, eps, 0, B1[0], B2[0], hA, gid, out);
    k_layer<<<grid, 256, LAYER_SMEM>>>(hA,    eps, 1, B1[1], B2[1], hB, gid, out);
    k_layer<<<grid, 256, LAYER_SMEM>>>(hB,    eps, 2, B1[2], B2[2], nullptr, gid, out);
}

// round 11
// speedup vs baseline: 2.8857x; 1.0084x over previous
#include <cuda_runtime.h>
#include <cuda_bf16.h>
#include <cuda_fp16.h>

#define NN 50000
#define NE 800000
#define D  128
#define NG 128

#define SA 132   // pool-staging row stride (floats)
#define SW 136   // bf16 row stride for A tiles
#define TM 32    // tile rows per block

// ---------------- device scratch ----------------
__device__ __half g_h0[NN * D];   // fp16 feats
__device__ __half g_hA[NN * D];
__device__ __half g_hB[NN * D];
__device__ int   g_beg[NN];
__device__ int   g_pos[NN];
__device__ int   g_cnt[NN];
__device__ int   g_col[NE];
__device__ int   g_total;
// fragment-ordered weights: [layer][gemm][cb(16)][kk(8)][lane(32)] = {bh0,bh1,bl0,bl1}
__device__ uint4 g_wfrag[3][2][16][8][32];

#define SCAN_B 98
#define WFRAG_N (6 * 16 * 8 * 32)   // 24576
#define FCONV_N (NN * D / 4)        // 1,600,000

// split float2 -> bf16x2 hi (ret) + bf16x2 lo (out)
__device__ __forceinline__ unsigned sp2(float2 x, unsigned& lo) {
    __nv_bfloat162 h = __float22bfloat162_rn(x);
    unsigned hu = *reinterpret_cast<unsigned*>(&h);
    float hx = __uint_as_float(hu << 16);
    float hy = __uint_as_float(hu & 0xffff0000u);
    __nv_bfloat162 l = __float22bfloat162_rn(make_float2(x.x - hx, x.y - hy));
    lo = *reinterpret_cast<unsigned*>(&l);
    return hu;
}

// ---------------- init: wfrag pack + feats->fp16 + zero cnt/out/total ----------------
__global__ void k_init(const float* __restrict__ feats,
                       const float* __restrict__ W10, const float* __restrict__ W20,
                       const float* __restrict__ W11, const float* __restrict__ W21,
                       const float* __restrict__ W12, const float* __restrict__ W22,
                       float* __restrict__ out) {
    int i = blockIdx.x * 256 + threadIdx.x;
    if (i < FCONV_N) {
        int j = i * 4;
        float4 v = __ldg((const float4*)&feats[j]);
        __half2 h0 = __floats2half2_rn(v.x, v.y);
        __half2 h1 = __floats2half2_rn(v.z, v.w);
        *(uint2*)&g_h0[j] = make_uint2(*(unsigned*)&h0, *(unsigned*)&h1);
    } else if (i < FCONV_N + WFRAG_N) {
        int w = i - FCONV_N;
        int which = w >> 12;            // 6 weights x 4096 frags
        int rem   = w & 4095;
        int cb    = rem >> 8;           // 16 col-groups
        int kk    = (rem >> 5) & 7;     // 8 k-steps
        int lane  = rem & 31;
        int grp = lane >> 2, qid = lane & 3;
        const float* W = (which == 0) ? W10 : (which == 1) ? W20 : (which == 2) ? W11
                        : (which == 3) ? W21 : (which == 4) ? W12 : W22;
        int layer = which >> 1, g = which & 1;
        int n  = cb * 8 + grp;
        int k0 = kk * 16 + 2 * qid;
        float x0 = __ldg(&W[(k0)     * 128 + n]);
        float x1 = __ldg(&W[(k0 + 1) * 128 + n]);
        float x2 = __ldg(&W[(k0 + 8) * 128 + n]);
        float x3 = __ldg(&W[(k0 + 9) * 128 + n]);
        unsigned bl0, bl1;
        unsigned bh0 = sp2(make_float2(x0, x1), bl0);
        unsigned bh1 = sp2(make_float2(x2, x3), bl1);
        g_wfrag[layer][g][cb][kk][lane] = make_uint4(bh0, bh1, bl0, bl1);
    } else if (i < FCONV_N + WFRAG_N + NN) {
        g_cnt[i - FCONV_N - WFRAG_N] = 0;
    } else if (i < FCONV_N + WFRAG_N + NN + NG * D) {
        out[i - FCONV_N - WFRAG_N - NN] = 0.f;
    } else if (i == FCONV_N + WFRAG_N + NN + NG * D) {
        g_total = 0;
    }
}

// ---------------- CSR build ----------------
__global__ void k_count(const int* __restrict__ dst) {
    int e4 = blockIdx.x * blockDim.x + threadIdx.x;
    if (e4 * 4 < NE) {
        int4 d = __ldg((const int4*)dst + e4);
        atomicAdd(&g_cnt[d.x], 1);
        atomicAdd(&g_cnt[d.y], 1);
        atomicAdd(&g_cnt[d.z], 1);
        atomicAdd(&g_cnt[d.w], 1);
    }
}

// single-pass: block scan + atomic block base (segment order is irrelevant)
__global__ void k_assign() {
    int t = threadIdx.x, b = blockIdx.x;
    int i = b * 512 + t;
    int v = (i < NN) ? g_cnt[i] : 0;
    int x = v;
    #pragma unroll
    for (int o = 1; o < 32; o <<= 1) {
        int y = __shfl_up_sync(0xffffffffu, x, o);
        if ((t & 31) >= o) x += y;
    }
    __shared__ int ws[16];
    __shared__ int sbase;
    if ((t & 31) == 31) ws[t >> 5] = x;
    __syncthreads();
    if (t < 16) {
        int y = ws[t];
        #pragma unroll
        for (int o = 1; o < 16; o <<= 1) {
            int z = __shfl_up_sync(0xffffu, y, o);
            if (t >= o) y += z;
        }
        ws[t] = y;
    }
    __syncthreads();
    int off = (t >= 32) ? ws[(t >> 5) - 1] : 0;
    int incl = x + off;
    if (t == 511) sbase = atomicAdd(&g_total, incl);
    __syncthreads();
    if (i < NN) {
        int p = sbase + incl - v;
        g_beg[i] = p;
        g_pos[i] = p;
    }
}

__global__ void k_scatter(const int* __restrict__ src, const int* __restrict__ dst) {
    int e4 = blockIdx.x * blockDim.x + threadIdx.x;
    if (e4 * 4 < NE) {
        int4 d = __ldg((const int4*)dst + e4);
        int4 s = __ldg((const int4*)src + e4);
        g_col[atomicAdd(&g_pos[d.x], 1)] = s.x;
        g_col[atomicAdd(&g_pos[d.y], 1)] = s.y;
        g_col[atomicAdd(&g_pos[d.z], 1)] = s.z;
        g_col[atomicAdd(&g_pos[d.w], 1)] = s.w;
    }
}

// ---------------- fused layer ----------------
#define A_BYTES (2 * TM * SW * 2)   // Ah+Al bf16 = 17408 B (pool fp32 [32][SA]=16896 fits)
#define LAYER_SMEM A_BYTES

__device__ __forceinline__ void mma_bf16(float* c, const unsigned* a, const unsigned* b) {
    asm volatile("mma.sync.aligned.m16n8k16.row.col.f32.bf16.bf16.f32 "
        "{%0,%1,%2,%3}, {%4,%5,%6,%7}, {%8,%9}, {%0,%1,%2,%3};"
        : "+f"(c[0]), "+f"(c[1]), "+f"(c[2]), "+f"(c[3])
        : "r"(a[0]), "r"(a[1]), "r"(a[2]), "r"(a[3]), "r"(b[0]), "r"(b[1]));
}

// L2-only 8-byte load (4 halves); avoid polluting L1, which holds W fragments
__device__ __forceinline__ uint2 ldcg2(const uint2* p) {
    uint2 v;
    asm volatile("ld.global.cg.v2.u32 {%0,%1}, [%2];" : "=r"(v.x), "=r"(v.y) : "l"(p));
    return v;
}

__device__ __forceinline__ void acc4(float4& a, uint2 u) {
    float2 f0 = __half22float2(*reinterpret_cast<__half2*>(&u.x));
    float2 f1 = __half22float2(*reinterpret_cast<__half2*>(&u.y));
    a.x += f0.x; a.y += f0.y; a.z += f1.x; a.w += f1.y;
}

__global__ void __launch_bounds__(256, 4)   // 64 regs/thread — NO spills (R6 lesson)
k_layer(const __half* __restrict__ hin, const float* __restrict__ eps, int layer,
        const float* __restrict__ B1, const float* __restrict__ B2,
        __half* __restrict__ hout,
        const int* __restrict__ gid, float* __restrict__ out) {
    extern __shared__ float sm[];
    __nv_bfloat16* Ah = (__nv_bfloat16*)sm;          // [TM][SW]
    __nv_bfloat16* Al = Ah + TM * SW;
    float* Ps = sm;                                  // pool staging union [TM][SA]
    __shared__ int s_row;

    const int t    = threadIdx.x;
    const int wid  = t >> 5;       // 0..7
    const int lane = t & 31;
    const int wn   = wid;          // cols wn*16..+15, rows 0..31 (all warps)
    const int grp  = lane >> 2;
    const int qid  = lane & 3;
    const int row0 = blockIdx.x * TM;

    if (t == 0) s_row = 8;
    float ev = 1.0f + __ldg(&eps[layer]);
    __syncthreads();

    // ---- gather z (dynamic row stealing), split to bf16 hi/lo tiles ----
    {
        const uint2* hv = (const uint2*)hin;    // 32 uint2 (128 halves) per row
        int r = wid;                            // first 8 rows static
        while (r < TM) {
            int node = row0 + r;
            float4 a = make_float4(0.f, 0.f, 0.f, 0.f);
            if (node < NN) {
                acc4(a, ldcg2(&hv[node * 32 + lane]));
                a.x *= ev; a.y *= ev; a.z *= ev; a.w *= ev;
                int jb = g_beg[node];
                int je = jb + g_cnt[node];
                int j = jb;
                for (; j + 4 <= je; j += 4) {
                    int s0 = g_col[j], s1 = g_col[j + 1], s2 = g_col[j + 2], s3 = g_col[j + 3];
                    uint2 x0 = ldcg2(&hv[s0 * 32 + lane]);
                    uint2 x1 = ldcg2(&hv[s1 * 32 + lane]);
                    uint2 x2 = ldcg2(&hv[s2 * 32 + lane]);
                    uint2 x3 = ldcg2(&hv[s3 * 32 + lane]);
                    acc4(a, x0); acc4(a, x1); acc4(a, x2); acc4(a, x3);
                }
                for (; j < je; j++) {
                    acc4(a, ldcg2(&hv[g_col[j] * 32 + lane]));
                }
            }
            unsigned l0, l1;
            unsigned h0 = sp2(make_float2(a.x, a.y), l0);
            unsigned h1 = sp2(make_float2(a.z, a.w), l1);
            *(uint2*)&Ah[r * SW + lane * 4] = make_uint2(h0, h1);
            *(uint2*)&Al[r * SW + lane * 4] = make_uint2(l0, l1);
            if (lane == 0) r = atomicAdd(&s_row, 1);
            r = __shfl_sync(0xffffffffu, r, 0);
        }
    }
    __syncthreads();

    float acc[2][2][4];
    #pragma unroll
    for (int mt = 0; mt < 2; mt++)
        #pragma unroll
        for (int nt = 0; nt < 2; nt++)
            #pragma unroll
            for (int q = 0; q < 4; q++) acc[mt][nt][q] = 0.f;

    // ---- GEMM 1: LDS A-frags + LDG.128 W-frags (L1-resident) + HMMA ----
    #pragma unroll 2
    for (int kk = 0; kk < 8; kk++) {
        int k0 = kk * 16;
        unsigned ah[2][4], al[2][4];
        #pragma unroll
        for (int mt = 0; mt < 2; mt++) {
            const __nv_bfloat16* ap = &Ah[(mt * 16 + grp) * SW + k0 + 2 * qid];
            const __nv_bfloat16* aq = &Al[(mt * 16 + grp) * SW + k0 + 2 * qid];
            ah[mt][0] = *(const unsigned*)ap;
            ah[mt][1] = *(const unsigned*)(ap + 8 * SW);
            ah[mt][2] = *(const unsigned*)(ap + 8);
            ah[mt][3] = *(const unsigned*)(ap + 8 * SW + 8);
            al[mt][0] = *(const unsigned*)aq;
            al[mt][1] = *(const unsigned*)(aq + 8 * SW);
            al[mt][2] = *(const unsigned*)(aq + 8);
            al[mt][3] = *(const unsigned*)(aq + 8 * SW + 8);
        }
        #pragma unroll
        for (int nt = 0; nt < 2; nt++) {
            uint4 f = __ldg(&g_wfrag[layer][0][wn * 2 + nt][kk][lane]);
            unsigned bh[2] = {f.x, f.y};
            unsigned bl[2] = {f.z, f.w};
            #pragma unroll
            for (int mt = 0; mt < 2; mt++) {
                mma_bf16(acc[mt][nt], ah[mt], bh);
                mma_bf16(acc[mt][nt], al[mt], bh);
                mma_bf16(acc[mt][nt], ah[mt], bl);
            }
        }
    }

    __syncthreads();

    // ---- epilogue 1: relu + split -> Ah/Al ----
    #pragma unroll
    for (int mt = 0; mt < 2; mt++) {
        int r0 = mt * 16 + grp;
        #pragma unroll
        for (int nt = 0; nt < 2; nt++) {
            int c = wn * 16 + nt * 8 + qid * 2;
            float b0 = __ldg(&B1[c]);
            float b1v = __ldg(&B1[c + 1]);
            float2 v0 = make_float2(fmaxf(acc[mt][nt][0] + b0, 0.f), fmaxf(acc[mt][nt][1] + b1v, 0.f));
            float2 v1 = make_float2(fmaxf(acc[mt][nt][2] + b0, 0.f), fmaxf(acc[mt][nt][3] + b1v, 0.f));
            unsigned l0, l1;
            unsigned h0 = sp2(v0, l0);
            unsigned h1 = sp2(v1, l1);
            *(unsigned*)&Ah[r0 * SW + c] = h0;
            *(unsigned*)&Al[r0 * SW + c] = l0;
            *(unsigned*)&Ah[(r0 + 8) * SW + c] = h1;
            *(unsigned*)&Al[(r0 + 8) * SW + c] = l1;
        }
    }
    __syncthreads();

    #pragma unroll
    for (int mt = 0; mt < 2; mt++)
        #pragma unroll
        for (int nt = 0; nt < 2; nt++)
            #pragma unroll
            for (int q = 0; q < 4; q++) acc[mt][nt][q] = 0.f;

    // ---- GEMM 2 ----
    #pragma unroll 2
    for (int kk = 0; kk < 8; kk++) {
        int k0 = kk * 16;
        unsigned ah[2][4], al[2][4];
        #pragma unroll
        for (int mt = 0; mt < 2; mt++) {
            const __nv_bfloat16* ap = &Ah[(mt * 16 + grp) * SW + k0 + 2 * qid];
            const __nv_bfloat16* aq = &Al[(mt * 16 + grp) * SW + k0 + 2 * qid];
            ah[mt][0] = *(const unsigned*)ap;
            ah[mt][1] = *(const unsigned*)(ap + 8 * SW);
            ah[mt][2] = *(const unsigned*)(ap + 8);
            ah[mt][3] = *(const unsigned*)(ap + 8 * SW + 8);
            al[mt][0] = *(const unsigned*)aq;
            al[mt][1] = *(const unsigned*)(aq + 8 * SW);
            al[mt][2] = *(const unsigned*)(aq + 8);
            al[mt][3] = *(const unsigned*)(aq + 8 * SW + 8);
        }
        #pragma unroll
        for (int nt = 0; nt < 2; nt++) {
            uint4 f = __ldg(&g_wfrag[layer][1][wn * 2 + nt][kk][lane]);
            unsigned bh[2] = {f.x, f.y};
            unsigned bl[2] = {f.z, f.w};
            #pragma unroll
            for (int mt = 0; mt < 2; mt++) {
                mma_bf16(acc[mt][nt], ah[mt], bh);
                mma_bf16(acc[mt][nt], al[mt], bh);
                mma_bf16(acc[mt][nt], ah[mt], bl);
            }
        }
    }

    // ---- epilogue 2 ----
    if (hout) {
        #pragma unroll
        for (int mt = 0; mt < 2; mt++) {
            int r0 = row0 + mt * 16 + grp;
            #pragma unroll
            for (int nt = 0; nt < 2; nt++) {
                int c = wn * 16 + nt * 8 + qid * 2;
                float b0 = __ldg(&B2[c]);
                float b1v = __ldg(&B2[c + 1]);
                if (r0 < NN) {
                    __half2 o = __floats2half2_rn(acc[mt][nt][0] + b0, acc[mt][nt][1] + b1v);
                    *(unsigned*)&hout[r0 * 128 + c] = *(unsigned*)&o;
                }
                if (r0 + 8 < NN) {
                    __half2 o = __floats2half2_rn(acc[mt][nt][2] + b0, acc[mt][nt][3] + b1v);
                    *(unsigned*)&hout[(r0 + 8) * 128 + c] = *(unsigned*)&o;
                }
            }
        }
    } else {
        __syncthreads();   // Ah/Al no longer needed; reuse as fp32 pool staging
        #pragma unroll
        for (int mt = 0; mt < 2; mt++) {
            int r0 = mt * 16 + grp;
            #pragma unroll
            for (int nt = 0; nt < 2; nt++) {
                int c = wn * 16 + nt * 8 + qid * 2;
                float b0 = __ldg(&B2[c]);
                float b1v = __ldg(&B2[c + 1]);
                *(float2*)&Ps[r0 * SA + c] =
                    make_float2(acc[mt][nt][0] + b0, acc[mt][nt][1] + b1v);
                *(float2*)&Ps[(r0 + 8) * SA + c] =
                    make_float2(acc[mt][nt][2] + b0, acc[mt][nt][3] + b1v);
            }
        }
        __syncthreads();
        int gg = t >> 7;       // 2 groups of 16 rows
        int c  = t & 127;
        float pacc = 0.f;
        int cur = -1;
        for (int r = gg * 16; r < gg * 16 + 16; r++) {
            int node = row0 + r;
            if (node >= NN) break;
            int g = __ldg(&gid[node]);
            if (g != cur) {
                if (cur >= 0) atomicAdd(&out[cur * 128 + c], pacc);
                cur = g;
                pacc = 0.f;
            }
            pacc += Ps[r * SA + c];
        }
        if (cur >= 0) atomicAdd(&out[cur * 128 + c], pacc);
    }
}

// ---------------- launch ----------------
extern "C" void kernel_launch(void* const* d_in, const int* in_sizes, int n_in,
                              void* d_out, int out_size) {
    const float* feats = (const float*)d_in[0];
    const int*   esrc  = (const int*)d_in[1];
    const int*   edst  = (const int*)d_in[2];
    const int*   gid   = (const int*)d_in[3];
    const float* eps   = (const float*)d_in[4];
    const float* W1[3] = {(const float*)d_in[5],  (const float*)d_in[9],  (const float*)d_in[13]};
    const float* B1[3] = {(const float*)d_in[6],  (const float*)d_in[10], (const float*)d_in[14]};
    const float* W2[3] = {(const float*)d_in[7],  (const float*)d_in[11], (const float*)d_in[15]};
    const float* B2[3] = {(const float*)d_in[8],  (const float*)d_in[12], (const float*)d_in[16]};
    float* out = (float*)d_out;
    (void)in_sizes; (void)n_in; (void)out_size;

    cudaFuncSetAttribute(k_layer, cudaFuncAttributeMaxDynamicSharedMemorySize, LAYER_SMEM);

    __half* h0; cudaGetSymbolAddress((void**)&h0, g_h0);
    __half* hA; cudaGetSymbolAddress((void**)&hA, g_hA);
    __half* hB; cudaGetSymbolAddress((void**)&hB, g_hB);

    int initN = FCONV_N + WFRAG_N + NN + NG * D + 1;
    k_init<<<(initN + 255) / 256, 256>>>(feats, W1[0], W2[0], W1[1], W2[1], W1[2], W2[2], out);

    k_count<<<(NE / 4 + 255) / 256, 256>>>(edst);
    k_assign<<<SCAN_B, 512>>>();
    k_scatter<<<(NE / 4 + 255) / 256, 256>>>(esrc, edst);

    int grid = (NN + TM - 1) / TM;
    k_layer<<<grid, 256, LAYER_SMEM>>>(h0, eps, 0, B1[0], B2[0], hA, gid, out);
    k_layer<<<grid, 256, LAYER_SMEM>>>(hA, eps, 1, B1[1], B2[1], hB, gid, out);
    k_layer<<<grid, 256, LAYER_SMEM>>>(hB, eps, 2, B1[2], B2[2], nullptr, gid, out);
}

// round 12
// speedup vs baseline: 3.3418x; 1.1581x over previous
#include <cuda_runtime.h>
#include <cuda_fp16.h>

#define NN 50000
#define NE 800000
#define D  128
#define NG 128

#define SA 132   // pool-staging row stride (floats)
#define SW 136   // fp16 row stride for A tile
#define TM 32    // tile rows per block

// ---------------- device scratch ----------------
__device__ __half g_h0[NN * D];   // fp16 feats
__device__ __half g_hA[NN * D];
__device__ __half g_hB[NN * D];
__device__ int   g_beg[NN];
__device__ int   g_pos[NN];
__device__ int   g_cnt[NN];
__device__ int   g_col[NE];
__device__ int   g_total;
// fragment-ordered weights (fp16 hi/lo): [layer][gemm][cb(16)][kk(8)][lane(32)] = {bh0,bh1,bl0,bl1}
__device__ uint4 g_wfrag[3][2][16][8][32];

#define SCAN_B 98
#define WFRAG_N (6 * 16 * 8 * 32)   // 24576
#define FCONV_N (NN * D / 4)        // 1,600,000

// split float2 -> fp16x2 hi (ret) + fp16x2 lo (out); w = hi + lo exact to ~2^-22
__device__ __forceinline__ unsigned sp2h(float2 x, unsigned& lo) {
    __half2 h = __floats2half2_rn(x.x, x.y);
    unsigned hu = *reinterpret_cast<unsigned*>(&h);
    float2 hf = __half22float2(h);
    __half2 l = __floats2half2_rn(x.x - hf.x, x.y - hf.y);
    lo = *reinterpret_cast<unsigned*>(&l);
    return hu;
}

// ---------------- init: wfrag pack + feats->fp16 + zero cnt/out/total ----------------
__global__ void k_init(const float* __restrict__ feats,
                       const float* __restrict__ W10, const float* __restrict__ W20,
                       const float* __restrict__ W11, const float* __restrict__ W21,
                       const float* __restrict__ W12, const float* __restrict__ W22,
                       float* __restrict__ out) {
    int i = blockIdx.x * 256 + threadIdx.x;
    if (i < FCONV_N) {
        int j = i * 4;
        float4 v = __ldg((const float4*)&feats[j]);
        __half2 h0 = __floats2half2_rn(v.x, v.y);
        __half2 h1 = __floats2half2_rn(v.z, v.w);
        *(uint2*)&g_h0[j] = make_uint2(*(unsigned*)&h0, *(unsigned*)&h1);
    } else if (i < FCONV_N + WFRAG_N) {
        int w = i - FCONV_N;
        int which = w >> 12;            // 6 weights x 4096 frags
        int rem   = w & 4095;
        int cb    = rem >> 8;           // 16 col-groups
        int kk    = (rem >> 5) & 7;     // 8 k-steps
        int lane  = rem & 31;
        int grp = lane >> 2, qid = lane & 3;
        const float* W = (which == 0) ? W10 : (which == 1) ? W20 : (which == 2) ? W11
                        : (which == 3) ? W21 : (which == 4) ? W12 : W22;
        int layer = which >> 1, g = which & 1;
        int n  = cb * 8 + grp;
        int k0 = kk * 16 + 2 * qid;
        float x0 = __ldg(&W[(k0)     * 128 + n]);
        float x1 = __ldg(&W[(k0 + 1) * 128 + n]);
        float x2 = __ldg(&W[(k0 + 8) * 128 + n]);
        float x3 = __ldg(&W[(k0 + 9) * 128 + n]);
        unsigned bl0, bl1;
        unsigned bh0 = sp2h(make_float2(x0, x1), bl0);
        unsigned bh1 = sp2h(make_float2(x2, x3), bl1);
        g_wfrag[layer][g][cb][kk][lane] = make_uint4(bh0, bh1, bl0, bl1);
    } else if (i < FCONV_N + WFRAG_N + NN) {
        g_cnt[i - FCONV_N - WFRAG_N] = 0;
    } else if (i < FCONV_N + WFRAG_N + NN + NG * D) {
        out[i - FCONV_N - WFRAG_N - NN] = 0.f;
    } else if (i == FCONV_N + WFRAG_N + NN + NG * D) {
        g_total = 0;
    }
}

// ---------------- CSR build ----------------
__global__ void k_count(const int* __restrict__ dst) {
    int e4 = blockIdx.x * blockDim.x + threadIdx.x;
    if (e4 * 4 < NE) {
        int4 d = __ldg((const int4*)dst + e4);
        atomicAdd(&g_cnt[d.x], 1);
        atomicAdd(&g_cnt[d.y], 1);
        atomicAdd(&g_cnt[d.z], 1);
        atomicAdd(&g_cnt[d.w], 1);
    }
}

// single-pass: block scan + atomic block base (segment order is irrelevant)
__global__ void k_assign() {
    int t = threadIdx.x, b = blockIdx.x;
    int i = b * 512 + t;
    int v = (i < NN) ? g_cnt[i] : 0;
    int x = v;
    #pragma unroll
    for (int o = 1; o < 32; o <<= 1) {
        int y = __shfl_up_sync(0xffffffffu, x, o);
        if ((t & 31) >= o) x += y;
    }
    __shared__ int ws[16];
    __shared__ int sbase;
    if ((t & 31) == 31) ws[t >> 5] = x;
    __syncthreads();
    if (t < 16) {
        int y = ws[t];
        #pragma unroll
        for (int o = 1; o < 16; o <<= 1) {
            int z = __shfl_up_sync(0xffffu, y, o);
            if (t >= o) y += z;
        }
        ws[t] = y;
    }
    __syncthreads();
    int off = (t >= 32) ? ws[(t >> 5) - 1] : 0;
    int incl = x + off;
    if (t == 511) sbase = atomicAdd(&g_total, incl);
    __syncthreads();
    if (i < NN) {
        int p = sbase + incl - v;
        g_beg[i] = p;
        g_pos[i] = p;
    }
}

__global__ void k_scatter(const int* __restrict__ src, const int* __restrict__ dst) {
    int e4 = blockIdx.x * blockDim.x + threadIdx.x;
    if (e4 * 4 < NE) {
        int4 d = __ldg((const int4*)dst + e4);
        int4 s = __ldg((const int4*)src + e4);
        g_col[atomicAdd(&g_pos[d.x], 1)] = s.x;
        g_col[atomicAdd(&g_pos[d.y], 1)] = s.y;
        g_col[atomicAdd(&g_pos[d.z], 1)] = s.z;
        g_col[atomicAdd(&g_pos[d.w], 1)] = s.w;
    }
}

// ---------------- fused layer ----------------
// smem: union of A fp16 tile [TM][SW] (8704 B) and pool fp32 staging [TM][SA] (16896 B)
#define LAYER_SMEM (TM * SA * 4)   // 16896

__device__ __forceinline__ void mma_f16(float* c, const unsigned* a, const unsigned* b) {
    asm volatile("mma.sync.aligned.m16n8k16.row.col.f32.f16.f16.f32 "
        "{%0,%1,%2,%3}, {%4,%5,%6,%7}, {%8,%9}, {%0,%1,%2,%3};"
        : "+f"(c[0]), "+f"(c[1]), "+f"(c[2]), "+f"(c[3])
        : "r"(a[0]), "r"(a[1]), "r"(a[2]), "r"(a[3]), "r"(b[0]), "r"(b[1]));
}

// L2-only 8-byte load (4 halves); avoid polluting L1, which holds W fragments
__device__ __forceinline__ uint2 ldcg2(const uint2* p) {
    uint2 v;
    asm volatile("ld.global.cg.v2.u32 {%0,%1}, [%2];" : "=r"(v.x), "=r"(v.y) : "l"(p));
    return v;
}

__device__ __forceinline__ void acc4(float4& a, uint2 u) {
    float2 f0 = __half22float2(*reinterpret_cast<__half2*>(&u.x));
    float2 f1 = __half22float2(*reinterpret_cast<__half2*>(&u.y));
    a.x += f0.x; a.y += f0.y; a.z += f1.x; a.w += f1.y;
}

__global__ void __launch_bounds__(256, 4)   // 64 regs/thread — NO spills (R6 lesson)
k_layer(const __half* __restrict__ hin, const float* __restrict__ eps, int layer,
        const float* __restrict__ B1, const float* __restrict__ B2,
        __half* __restrict__ hout,
        const int* __restrict__ gid, float* __restrict__ out) {
    extern __shared__ float sm[];
    __half* As = (__half*)sm;                        // [TM][SW] fp16
    float* Ps = sm;                                  // pool staging union [TM][SA]
    __shared__ int s_row;

    const int t    = threadIdx.x;
    const int wid  = t >> 5;       // 0..7
    const int lane = t & 31;
    const int wn   = wid;          // cols wn*16..+15, rows 0..31 (all warps)
    const int grp  = lane >> 2;
    const int qid  = lane & 3;
    const int row0 = blockIdx.x * TM;

    if (t == 0) s_row = 8;
    float ev = 1.0f + __ldg(&eps[layer]);
    __syncthreads();

    // ---- gather z (dynamic row stealing), fp32 accum -> fp16 tile ----
    {
        const uint2* hv = (const uint2*)hin;    // 32 uint2 (128 halves) per row
        int r = wid;                            // first 8 rows static
        while (r < TM) {
            int node = row0 + r;
            float4 a = make_float4(0.f, 0.f, 0.f, 0.f);
            if (node < NN) {
                acc4(a, ldcg2(&hv[node * 32 + lane]));
                a.x *= ev; a.y *= ev; a.z *= ev; a.w *= ev;
                int jb = g_beg[node];
                int je = jb + g_cnt[node];
                int j = jb;
                for (; j + 8 <= je; j += 8) {      // MLP=8: halve latency exposure
                    int s0 = g_col[j],     s1 = g_col[j + 1], s2 = g_col[j + 2], s3 = g_col[j + 3];
                    int s4 = g_col[j + 4], s5 = g_col[j + 5], s6 = g_col[j + 6], s7 = g_col[j + 7];
                    uint2 x0 = ldcg2(&hv[s0 * 32 + lane]);
                    uint2 x1 = ldcg2(&hv[s1 * 32 + lane]);
                    uint2 x2 = ldcg2(&hv[s2 * 32 + lane]);
                    uint2 x3 = ldcg2(&hv[s3 * 32 + lane]);
                    uint2 x4 = ldcg2(&hv[s4 * 32 + lane]);
                    uint2 x5 = ldcg2(&hv[s5 * 32 + lane]);
                    uint2 x6 = ldcg2(&hv[s6 * 32 + lane]);
                    uint2 x7 = ldcg2(&hv[s7 * 32 + lane]);
                    acc4(a, x0); acc4(a, x1); acc4(a, x2); acc4(a, x3);
                    acc4(a, x4); acc4(a, x5); acc4(a, x6); acc4(a, x7);
                }
                for (; j + 4 <= je; j += 4) {
                    int s0 = g_col[j], s1 = g_col[j + 1], s2 = g_col[j + 2], s3 = g_col[j + 3];
                    uint2 x0 = ldcg2(&hv[s0 * 32 + lane]);
                    uint2 x1 = ldcg2(&hv[s1 * 32 + lane]);
                    uint2 x2 = ldcg2(&hv[s2 * 32 + lane]);
                    uint2 x3 = ldcg2(&hv[s3 * 32 + lane]);
                    acc4(a, x0); acc4(a, x1); acc4(a, x2); acc4(a, x3);
                }
                for (; j < je; j++) {
                    acc4(a, ldcg2(&hv[g_col[j] * 32 + lane]));
                }
            }
            __half2 h0 = __floats2half2_rn(a.x, a.y);
            __half2 h1 = __floats2half2_rn(a.z, a.w);
            *(uint2*)&As[r * SW + lane * 4] = make_uint2(*(unsigned*)&h0, *(unsigned*)&h1);
            if (lane == 0) r = atomicAdd(&s_row, 1);
            r = __shfl_sync(0xffffffffu, r, 0);
        }
    }
    __syncthreads();

    float acc[2][2][4];
    #pragma unroll
    for (int mt = 0; mt < 2; mt++)
        #pragma unroll
        for (int nt = 0; nt < 2; nt++)
            #pragma unroll
            for (int q = 0; q < 4; q++) acc[mt][nt][q] = 0.f;

    // ---- GEMM 1: fp16 A (plain) x fp16 W (hi+lo), 2 MMA terms ----
    #pragma unroll 2
    for (int kk = 0; kk < 8; kk++) {
        int k0 = kk * 16;
        unsigned ah[2][4];
        #pragma unroll
        for (int mt = 0; mt < 2; mt++) {
            const __half* ap = &As[(mt * 16 + grp) * SW + k0 + 2 * qid];
            ah[mt][0] = *(const unsigned*)ap;
            ah[mt][1] = *(const unsigned*)(ap + 8 * SW);
            ah[mt][2] = *(const unsigned*)(ap + 8);
            ah[mt][3] = *(const unsigned*)(ap + 8 * SW + 8);
        }
        #pragma unroll
        for (int nt = 0; nt < 2; nt++) {
            uint4 f = __ldg(&g_wfrag[layer][0][wn * 2 + nt][kk][lane]);
            unsigned bh[2] = {f.x, f.y};
            unsigned bl[2] = {f.z, f.w};
            #pragma unroll
            for (int mt = 0; mt < 2; mt++) {
                mma_f16(acc[mt][nt], ah[mt], bh);
                mma_f16(acc[mt][nt], ah[mt], bl);
            }
        }
    }

    __syncthreads();

    // ---- epilogue 1: relu -> fp16 As ----
    #pragma unroll
    for (int mt = 0; mt < 2; mt++) {
        int r0 = mt * 16 + grp;
        #pragma unroll
        for (int nt = 0; nt < 2; nt++) {
            int c = wn * 16 + nt * 8 + qid * 2;
            float b0 = __ldg(&B1[c]);
            float b1v = __ldg(&B1[c + 1]);
            __half2 v0 = __floats2half2_rn(fmaxf(acc[mt][nt][0] + b0, 0.f),
                                           fmaxf(acc[mt][nt][1] + b1v, 0.f));
            __half2 v1 = __floats2half2_rn(fmaxf(acc[mt][nt][2] + b0, 0.f),
                                           fmaxf(acc[mt][nt][3] + b1v, 0.f));
            *(unsigned*)&As[r0 * SW + c] = *(unsigned*)&v0;
            *(unsigned*)&As[(r0 + 8) * SW + c] = *(unsigned*)&v1;
        }
    }
    __syncthreads();

    #pragma unroll
    for (int mt = 0; mt < 2; mt++)
        #pragma unroll
        for (int nt = 0; nt < 2; nt++)
            #pragma unroll
            for (int q = 0; q < 4; q++) acc[mt][nt][q] = 0.f;

    // ---- GEMM 2 ----
    #pragma unroll 2
    for (int kk = 0; kk < 8; kk++) {
        int k0 = kk * 16;
        unsigned ah[2][4];
        #pragma unroll
        for (int mt = 0; mt < 2; mt++) {
            const __half* ap = &As[(mt * 16 + grp) * SW + k0 + 2 * qid];
            ah[mt][0] = *(const unsigned*)ap;
            ah[mt][1] = *(const unsigned*)(ap + 8 * SW);
            ah[mt][2] = *(const unsigned*)(ap + 8);
            ah[mt][3] = *(const unsigned*)(ap + 8 * SW + 8);
        }
        #pragma unroll
        for (int nt = 0; nt < 2; nt++) {
            uint4 f = __ldg(&g_wfrag[layer][1][wn * 2 + nt][kk][lane]);
            unsigned bh[2] = {f.x, f.y};
            unsigned bl[2] = {f.z, f.w};
            #pragma unroll
            for (int mt = 0; mt < 2; mt++) {
                mma_f16(acc[mt][nt], ah[mt], bh);
                mma_f16(acc[mt][nt], ah[mt], bl);
            }
        }
    }

    // ---- epilogue 2 ----
    if (hout) {
        #pragma unroll
        for (int mt = 0; mt < 2; mt++) {
            int r0 = row0 + mt * 16 + grp;
            #pragma unroll
            for (int nt = 0; nt < 2; nt++) {
                int c = wn * 16 + nt * 8 + qid * 2;
                float b0 = __ldg(&B2[c]);
                float b1v = __ldg(&B2[c + 1]);
                if (r0 < NN) {
                    __half2 o = __floats2half2_rn(acc[mt][nt][0] + b0, acc[mt][nt][1] + b1v);
                    *(unsigned*)&hout[r0 * 128 + c] = *(unsigned*)&o;
                }
                if (r0 + 8 < NN) {
                    __half2 o = __floats2half2_rn(acc[mt][nt][2] + b0, acc[mt][nt][3] + b1v);
                    *(unsigned*)&hout[(r0 + 8) * 128 + c] = *(unsigned*)&o;
                }
            }
        }
    } else {
        __syncthreads();   // As no longer needed; reuse as fp32 pool staging
        #pragma unroll
        for (int mt = 0; mt < 2; mt++) {
            int r0 = mt * 16 + grp;
            #pragma unroll
            for (int nt = 0; nt < 2; nt++) {
                int c = wn * 16 + nt * 8 + qid * 2;
                float b0 = __ldg(&B2[c]);
                float b1v = __ldg(&B2[c + 1]);
                *(float2*)&Ps[r0 * SA + c] =
                    make_float2(acc[mt][nt][0] + b0, acc[mt][nt][1] + b1v);
                *(float2*)&Ps[(r0 + 8) * SA + c] =
                    make_float2(acc[mt][nt][2] + b0, acc[mt][nt][3] + b1v);
            }
        }
        __syncthreads();
        int gg = t >> 7;       // 2 groups of 16 rows
        int c  = t & 127;
        float pacc = 0.f;
        int cur = -1;
        for (int r = gg * 16; r < gg * 16 + 16; r++) {
            int node = row0 + r;
            if (node >= NN) break;
            int g = __ldg(&gid[node]);
            if (g != cur) {
                if (cur >= 0) atomicAdd(&out[cur * 128 + c], pacc);
                cur = g;
                pacc = 0.f;
            }
            pacc += Ps[r * SA + c];
        }
        if (cur >= 0) atomicAdd(&out[cur * 128 + c], pacc);
    }
}

// ---------------- launch ----------------
extern "C" void kernel_launch(void* const* d_in, const int* in_sizes, int n_in,
                              void* d_out, int out_size) {
    const float* feats = (const float*)d_in[0];
    const int*   esrc  = (const int*)d_in[1];
    const int*   edst  = (const int*)d_in[2];
    const int*   gid   = (const int*)d_in[3];
    const float* eps   = (const float*)d_in[4];
    const float* W1[3] = {(const float*)d_in[5],  (const float*)d_in[9],  (const float*)d_in[13]};
    const float* B1[3] = {(const float*)d_in[6],  (const float*)d_in[10], (const float*)d_in[14]};
    const float* W2[3] = {(const float*)d_in[7],  (const float*)d_in[11], (const float*)d_in[15]};
    const float* B2[3] = {(const float*)d_in[8],  (const float*)d_in[12], (const float*)d_in[16]};
    float* out = (float*)d_out;
    (void)in_sizes; (void)n_in; (void)out_size;

    cudaFuncSetAttribute(k_layer, cudaFuncAttributeMaxDynamicSharedMemorySize, LAYER_SMEM);

    __half* h0; cudaGetSymbolAddress((void**)&h0, g_h0);
    __half* hA; cudaGetSymbolAddress((void**)&hA, g_hA);
    __half* hB; cudaGetSymbolAddress((void**)&hB, g_hB);

    int initN = FCONV_N + WFRAG_N + NN + NG * D + 1;
    k_init<<<(initN + 255) / 256, 256>>>(feats, W1[0], W2[0], W1[1], W2[1], W1[2], W2[2], out);

    k_count<<<(NE / 4 + 255) / 256, 256>>>(edst);
    k_assign<<<SCAN_B, 512>>>();
    k_scatter<<<(NE / 4 + 255) / 256, 256>>>(esrc, edst);

    int grid = (NN + TM - 1) / TM;
    k_layer<<<grid, 256, LAYER_SMEM>>>(h0, eps, 0, B1[0], B2[0], hA, gid, out);
    k_layer<<<grid, 256, LAYER_SMEM>>>(hA, eps, 1, B1[1], B2[1], hB, gid, out);
    k_layer<<<grid, 256, LAYER_SMEM>>>(hB, eps, 2, B1[2], B2[2], nullptr, gid, out);
}

// round 13
// speedup vs baseline: 3.4001x; 1.0175x over previous
#include <cuda_runtime.h>
#include <cuda_fp16.h>

#define NN 50000
#define NE 800000
#define D  128
#define NG 128

#define SA 132   // pool-staging row stride (floats)
#define SW 136   // fp16 row stride for A tile (272B rows -> conflict-free LDSM)
#define TM 32    // tile rows per block

// ---------------- device scratch ----------------
__device__ __half g_h0[NN * D];   // fp16 feats
__device__ __half g_hA[NN * D];
__device__ __half g_hB[NN * D];
__device__ int   g_beg[NN];
__device__ int   g_pos[NN];
__device__ int   g_cnt[NN];
__device__ int   g_col[NE];
__device__ int   g_total;
// fragment-ordered weights (fp16 hi/lo): [layer][gemm][cb(16)][kk(8)][lane(32)] = {bh0,bh1,bl0,bl1}
__device__ uint4 g_wfrag[3][2][16][8][32];

#define SCAN_B 98
#define WFRAG_N (6 * 16 * 8 * 32)   // 24576
#define FCONV_N (NN * D / 4)        // 1,600,000

// split float2 -> fp16x2 hi (ret) + fp16x2 lo (out); w = hi + lo exact to ~2^-22
__device__ __forceinline__ unsigned sp2h(float2 x, unsigned& lo) {
    __half2 h = __floats2half2_rn(x.x, x.y);
    unsigned hu = *reinterpret_cast<unsigned*>(&h);
    float2 hf = __half22float2(h);
    __half2 l = __floats2half2_rn(x.x - hf.x, x.y - hf.y);
    lo = *reinterpret_cast<unsigned*>(&l);
    return hu;
}

// ---------------- init: wfrag pack + feats->fp16 + zero cnt/out/total ----------------
__global__ void k_init(const float* __restrict__ feats,
                       const float* __restrict__ W10, const float* __restrict__ W20,
                       const float* __restrict__ W11, const float* __restrict__ W21,
                       const float* __restrict__ W12, const float* __restrict__ W22,
                       float* __restrict__ out) {
    int i = blockIdx.x * 256 + threadIdx.x;
    if (i < FCONV_N) {
        int j = i * 4;
        float4 v = __ldg((const float4*)&feats[j]);
        __half2 h0 = __floats2half2_rn(v.x, v.y);
        __half2 h1 = __floats2half2_rn(v.z, v.w);
        *(uint2*)&g_h0[j] = make_uint2(*(unsigned*)&h0, *(unsigned*)&h1);
    } else if (i < FCONV_N + WFRAG_N) {
        int w = i - FCONV_N;
        int which = w >> 12;            // 6 weights x 4096 frags
        int rem   = w & 4095;
        int cb    = rem >> 8;           // 16 col-groups
        int kk    = (rem >> 5) & 7;     // 8 k-steps
        int lane  = rem & 31;
        int grp = lane >> 2, qid = lane & 3;
        const float* W = (which == 0) ? W10 : (which == 1) ? W20 : (which == 2) ? W11
                        : (which == 3) ? W21 : (which == 4) ? W12 : W22;
        int layer = which >> 1, g = which & 1;
        int n  = cb * 8 + grp;
        int k0 = kk * 16 + 2 * qid;
        float x0 = __ldg(&W[(k0)     * 128 + n]);
        float x1 = __ldg(&W[(k0 + 1) * 128 + n]);
        float x2 = __ldg(&W[(k0 + 8) * 128 + n]);
        float x3 = __ldg(&W[(k0 + 9) * 128 + n]);
        unsigned bl0, bl1;
        unsigned bh0 = sp2h(make_float2(x0, x1), bl0);
        unsigned bh1 = sp2h(make_float2(x2, x3), bl1);
        g_wfrag[layer][g][cb][kk][lane] = make_uint4(bh0, bh1, bl0, bl1);
    } else if (i < FCONV_N + WFRAG_N + NN) {
        g_cnt[i - FCONV_N - WFRAG_N] = 0;
    } else if (i < FCONV_N + WFRAG_N + NN + NG * D) {
        out[i - FCONV_N - WFRAG_N - NN] = 0.f;
    } else if (i == FCONV_N + WFRAG_N + NN + NG * D) {
        g_total = 0;
    }
}

// ---------------- CSR build ----------------
__global__ void k_count(const int* __restrict__ dst) {
    int e4 = blockIdx.x * blockDim.x + threadIdx.x;
    if (e4 * 4 < NE) {
        int4 d = __ldg((const int4*)dst + e4);
        atomicAdd(&g_cnt[d.x], 1);
        atomicAdd(&g_cnt[d.y], 1);
        atomicAdd(&g_cnt[d.z], 1);
        atomicAdd(&g_cnt[d.w], 1);
    }
}

// single-pass: block scan + atomic block base (segment order is irrelevant)
__global__ void k_assign() {
    int t = threadIdx.x, b = blockIdx.x;
    int i = b * 512 + t;
    int v = (i < NN) ? g_cnt[i] : 0;
    int x = v;
    #pragma unroll
    for (int o = 1; o < 32; o <<= 1) {
        int y = __shfl_up_sync(0xffffffffu, x, o);
        if ((t & 31) >= o) x += y;
    }
    __shared__ int ws[16];
    __shared__ int sbase;
    if ((t & 31) == 31) ws[t >> 5] = x;
    __syncthreads();
    if (t < 16) {
        int y = ws[t];
        #pragma unroll
        for (int o = 1; o < 16; o <<= 1) {
            int z = __shfl_up_sync(0xffffu, y, o);
            if (t >= o) y += z;
        }
        ws[t] = y;
    }
    __syncthreads();
    int off = (t >= 32) ? ws[(t >> 5) - 1] : 0;
    int incl = x + off;
    if (t == 511) sbase = atomicAdd(&g_total, incl);
    __syncthreads();
    if (i < NN) {
        int p = sbase + incl - v;
        g_beg[i] = p;
        g_pos[i] = p;
    }
}

__global__ void k_scatter(const int* __restrict__ src, const int* __restrict__ dst) {
    int e4 = blockIdx.x * blockDim.x + threadIdx.x;
    if (e4 * 4 < NE) {
        int4 d = __ldg((const int4*)dst + e4);
        int4 s = __ldg((const int4*)src + e4);
        g_col[atomicAdd(&g_pos[d.x], 1)] = s.x;
        g_col[atomicAdd(&g_pos[d.y], 1)] = s.y;
        g_col[atomicAdd(&g_pos[d.z], 1)] = s.z;
        g_col[atomicAdd(&g_pos[d.w], 1)] = s.w;
    }
}

// ---------------- fused layer ----------------
// smem: union of A fp16 tile [TM][SW] (8704 B) and pool fp32 staging [TM][SA] (16896 B)
#define LAYER_SMEM (TM * SA * 4)   // 16896

__device__ __forceinline__ void mma_f16(float* c, const unsigned* a, const unsigned* b) {
    asm volatile("mma.sync.aligned.m16n8k16.row.col.f32.f16.f16.f32 "
        "{%0,%1,%2,%3}, {%4,%5,%6,%7}, {%8,%9}, {%0,%1,%2,%3};"
        : "+f"(c[0]), "+f"(c[1]), "+f"(c[2]), "+f"(c[3])
        : "r"(a[0]), "r"(a[1]), "r"(a[2]), "r"(a[3]), "r"(b[0]), "r"(b[1]));
}

// ldmatrix x4: loads full m16k16 A fragment (4 regs) in one instruction
__device__ __forceinline__ void ldsm4(unsigned* r, unsigned addr) {
    asm volatile("ldmatrix.sync.aligned.m8n8.x4.shared.b16 {%0,%1,%2,%3}, [%4];"
        : "=r"(r[0]), "=r"(r[1]), "=r"(r[2]), "=r"(r[3]) : "r"(addr));
}

// L2-only 8-byte load (4 halves); avoid polluting L1, which holds W fragments
__device__ __forceinline__ uint2 ldcg2(const uint2* p) {
    uint2 v;
    asm volatile("ld.global.cg.v2.u32 {%0,%1}, [%2];" : "=r"(v.x), "=r"(v.y) : "l"(p));
    return v;
}

__device__ __forceinline__ void acc4(float4& a, uint2 u) {
    float2 f0 = __half22float2(*reinterpret_cast<__half2*>(&u.x));
    float2 f1 = __half22float2(*reinterpret_cast<__half2*>(&u.y));
    a.x += f0.x; a.y += f0.y; a.z += f1.x; a.w += f1.y;
}

__global__ void __launch_bounds__(256, 4)   // 64 regs/thread — NO spills (R6 lesson)
k_layer(const __half* __restrict__ hin, const float* __restrict__ eps, int layer,
        const float* __restrict__ B1, const float* __restrict__ B2,
        __half* __restrict__ hout,
        const int* __restrict__ gid, float* __restrict__ out) {
    extern __shared__ float sm[];
    __half* As = (__half*)sm;                        // [TM][SW] fp16
    float* Ps = sm;                                  // pool staging union [TM][SA]
    __shared__ int s_row;

    const int t    = threadIdx.x;
    const int wid  = t >> 5;       // 0..7
    const int lane = t & 31;
    const int wn   = wid;          // cols wn*16..+15, rows 0..31 (all warps)
    const int grp  = lane >> 2;
    const int qid  = lane & 3;
    const int row0 = blockIdx.x * TM;

    if (t == 0) s_row = 8;
    float ev = 1.0f + __ldg(&eps[layer]);
    __syncthreads();

    // ---- gather z (dynamic row stealing), fp32 accum -> fp16 tile ----
    {
        const uint2* hv = (const uint2*)hin;    // 32 uint2 (128 halves) per row
        int r = wid;                            // first 8 rows static
        while (r < TM) {
            int node = row0 + r;
            float4 a = make_float4(0.f, 0.f, 0.f, 0.f);
            if (node < NN) {
                acc4(a, ldcg2(&hv[node * 32 + lane]));
                a.x *= ev; a.y *= ev; a.z *= ev; a.w *= ev;
                int jb = g_beg[node];
                int je = jb + g_cnt[node];
                int j = jb;
                for (; j + 8 <= je; j += 8) {      // MLP=8: halve latency exposure
                    int s0 = g_col[j],     s1 = g_col[j + 1], s2 = g_col[j + 2], s3 = g_col[j + 3];
                    int s4 = g_col[j + 4], s5 = g_col[j + 5], s6 = g_col[j + 6], s7 = g_col[j + 7];
                    uint2 x0 = ldcg2(&hv[s0 * 32 + lane]);
                    uint2 x1 = ldcg2(&hv[s1 * 32 + lane]);
                    uint2 x2 = ldcg2(&hv[s2 * 32 + lane]);
                    uint2 x3 = ldcg2(&hv[s3 * 32 + lane]);
                    uint2 x4 = ldcg2(&hv[s4 * 32 + lane]);
                    uint2 x5 = ldcg2(&hv[s5 * 32 + lane]);
                    uint2 x6 = ldcg2(&hv[s6 * 32 + lane]);
                    uint2 x7 = ldcg2(&hv[s7 * 32 + lane]);
                    acc4(a, x0); acc4(a, x1); acc4(a, x2); acc4(a, x3);
                    acc4(a, x4); acc4(a, x5); acc4(a, x6); acc4(a, x7);
                }
                for (; j + 4 <= je; j += 4) {
                    int s0 = g_col[j], s1 = g_col[j + 1], s2 = g_col[j + 2], s3 = g_col[j + 3];
                    uint2 x0 = ldcg2(&hv[s0 * 32 + lane]);
                    uint2 x1 = ldcg2(&hv[s1 * 32 + lane]);
                    uint2 x2 = ldcg2(&hv[s2 * 32 + lane]);
                    uint2 x3 = ldcg2(&hv[s3 * 32 + lane]);
                    acc4(a, x0); acc4(a, x1); acc4(a, x2); acc4(a, x3);
                }
                for (; j < je; j++) {
                    acc4(a, ldcg2(&hv[g_col[j] * 32 + lane]));
                }
            }
            __half2 h0 = __floats2half2_rn(a.x, a.y);
            __half2 h1 = __floats2half2_rn(a.z, a.w);
            *(uint2*)&As[r * SW + lane * 4] = make_uint2(*(unsigned*)&h0, *(unsigned*)&h1);
            if (lane == 0) r = atomicAdd(&s_row, 1);
            r = __shfl_sync(0xffffffffu, r, 0);
        }
    }
    __syncthreads();

    // per-lane LDSM base address: row = (lane&7) + ((lane>>3)&1)*8, col = (lane>>4)*8
    const unsigned as_shared = (unsigned)__cvta_generic_to_shared(As);
    const unsigned lds_base = as_shared
        + (((lane & 7) + ((lane >> 3) & 1) * 8) * SW + ((lane >> 4) * 8)) * 2;

    float acc[2][2][4];
    #pragma unroll
    for (int mt = 0; mt < 2; mt++)
        #pragma unroll
        for (int nt = 0; nt < 2; nt++)
            #pragma unroll
            for (int q = 0; q < 4; q++) acc[mt][nt][q] = 0.f;

    // ---- GEMM 1: LDSM A + fp16 W (hi+lo), 2 MMA terms ----
    #pragma unroll 2
    for (int kk = 0; kk < 8; kk++) {
        unsigned ah[2][4];
        #pragma unroll
        for (int mt = 0; mt < 2; mt++)
            ldsm4(ah[mt], lds_base + (mt * 16 * SW + kk * 16) * 2);
        #pragma unroll
        for (int nt = 0; nt < 2; nt++) {
            uint4 f = __ldg(&g_wfrag[layer][0][wn * 2 + nt][kk][lane]);
            unsigned bh[2] = {f.x, f.y};
            unsigned bl[2] = {f.z, f.w};
            #pragma unroll
            for (int mt = 0; mt < 2; mt++) {
                mma_f16(acc[mt][nt], ah[mt], bh);
                mma_f16(acc[mt][nt], ah[mt], bl);
            }
        }
    }

    __syncthreads();

    // ---- epilogue 1: relu -> fp16 As ----
    #pragma unroll
    for (int mt = 0; mt < 2; mt++) {
        int r0 = mt * 16 + grp;
        #pragma unroll
        for (int nt = 0; nt < 2; nt++) {
            int c = wn * 16 + nt * 8 + qid * 2;
            float b0 = __ldg(&B1[c]);
            float b1v = __ldg(&B1[c + 1]);
            __half2 v0 = __floats2half2_rn(fmaxf(acc[mt][nt][0] + b0, 0.f),
                                           fmaxf(acc[mt][nt][1] + b1v, 0.f));
            __half2 v1 = __floats2half2_rn(fmaxf(acc[mt][nt][2] + b0, 0.f),
                                           fmaxf(acc[mt][nt][3] + b1v, 0.f));
            *(unsigned*)&As[r0 * SW + c] = *(unsigned*)&v0;
            *(unsigned*)&As[(r0 + 8) * SW + c] = *(unsigned*)&v1;
        }
    }
    __syncthreads();

    #pragma unroll
    for (int mt = 0; mt < 2; mt++)
        #pragma unroll
        for (int nt = 0; nt < 2; nt++)
            #pragma unroll
            for (int q = 0; q < 4; q++) acc[mt][nt][q] = 0.f;

    // ---- GEMM 2 ----
    #pragma unroll 2
    for (int kk = 0; kk < 8; kk++) {
        unsigned ah[2][4];
        #pragma unroll
        for (int mt = 0; mt < 2; mt++)
            ldsm4(ah[mt], lds_base + (mt * 16 * SW + kk * 16) * 2);
        #pragma unroll
        for (int nt = 0; nt < 2; nt++) {
            uint4 f = __ldg(&g_wfrag[layer][1][wn * 2 + nt][kk][lane]);
            unsigned bh[2] = {f.x, f.y};
            unsigned bl[2] = {f.z, f.w};
            #pragma unroll
            for (int mt = 0; mt < 2; mt++) {
                mma_f16(acc[mt][nt], ah[mt], bh);
                mma_f16(acc[mt][nt], ah[mt], bl);
            }
        }
    }

    // ---- epilogue 2 ----
    if (hout) {
        #pragma unroll
        for (int mt = 0; mt < 2; mt++) {
            int r0 = row0 + mt * 16 + grp;
            #pragma unroll
            for (int nt = 0; nt < 2; nt++) {
                int c = wn * 16 + nt * 8 + qid * 2;
                float b0 = __ldg(&B2[c]);
                float b1v = __ldg(&B2[c + 1]);
                if (r0 < NN) {
                    __half2 o = __floats2half2_rn(acc[mt][nt][0] + b0, acc[mt][nt][1] + b1v);
                    *(unsigned*)&hout[r0 * 128 + c] = *(unsigned*)&o;
                }
                if (r0 + 8 < NN) {
                    __half2 o = __floats2half2_rn(acc[mt][nt][2] + b0, acc[mt][nt][3] + b1v);
                    *(unsigned*)&hout[(r0 + 8) * 128 + c] = *(unsigned*)&o;
                }
            }
        }
    } else {
        __syncthreads();   // As no longer needed; reuse as fp32 pool staging
        #pragma unroll
        for (int mt = 0; mt < 2; mt++) {
            int r0 = mt * 16 + grp;
            #pragma unroll
            for (int nt = 0; nt < 2; nt++) {
                int c = wn * 16 + nt * 8 + qid * 2;
                float b0 = __ldg(&B2[c]);
                float b1v = __ldg(&B2[c + 1]);
                *(float2*)&Ps[r0 * SA + c] =
                    make_float2(acc[mt][nt][0] + b0, acc[mt][nt][1] + b1v);
                *(float2*)&Ps[(r0 + 8) * SA + c] =
                    make_float2(acc[mt][nt][2] + b0, acc[mt][nt][3] + b1v);
            }
        }
        __syncthreads();
        int gg = t >> 7;       // 2 groups of 16 rows
        int c  = t & 127;
        float pacc = 0.f;
        int cur = -1;
        for (int r = gg * 16; r < gg * 16 + 16; r++) {
            int node = row0 + r;
            if (node >= NN) break;
            int g = __ldg(&gid[node]);
            if (g != cur) {
                if (cur >= 0) atomicAdd(&out[cur * 128 + c], pacc);
                cur = g;
                pacc = 0.f;
            }
            pacc += Ps[r * SA + c];
        }
        if (cur >= 0) atomicAdd(&out[cur * 128 + c], pacc);
    }
}

// ---------------- launch ----------------
extern "C" void kernel_launch(void* const* d_in, const int* in_sizes, int n_in,
                              void* d_out, int out_size) {
    const float* feats = (const float*)d_in[0];
    const int*   esrc  = (const int*)d_in[1];
    const int*   edst  = (const int*)d_in[2];
    const int*   gid   = (const int*)d_in[3];
    const float* eps   = (const float*)d_in[4];
    const float* W1[3] = {(const float*)d_in[5],  (const float*)d_in[9],  (const float*)d_in[13]};
    const float* B1[3] = {(const float*)d_in[6],  (const float*)d_in[10], (const float*)d_in[14]};
    const float* W2[3] = {(const float*)d_in[7],  (const float*)d_in[11], (const float*)d_in[15]};
    const float* B2[3] = {(const float*)d_in[8],  (const float*)d_in[12], (const float*)d_in[16]};
    float* out = (float*)d_out;
    (void)in_sizes; (void)n_in; (void)out_size;

    cudaFuncSetAttribute(k_layer, cudaFuncAttributeMaxDynamicSharedMemorySize, LAYER_SMEM);

    __half* h0; cudaGetSymbolAddress((void**)&h0, g_h0);
    __half* hA; cudaGetSymbolAddress((void**)&hA, g_hA);
    __half* hB; cudaGetSymbolAddress((void**)&hB, g_hB);

    int initN = FCONV_N + WFRAG_N + NN + NG * D + 1;
    k_init<<<(initN + 255) / 256, 256>>>(feats, W1[0], W2[0], W1[1], W2[1], W1[2], W2[2], out);

    k_count<<<(NE / 4 + 255) / 256, 256>>>(edst);
    k_assign<<<SCAN_B, 512>>>();
    k_scatter<<<(NE / 4 + 255) / 256, 256>>>(esrc, edst);

    int grid = (NN + TM - 1) / TM;
    k_layer<<<grid, 256, LAYER_SMEM>>>(h0, eps, 0, B1[0], B2[0], hA, gid, out);
    k_layer<<<grid, 256, LAYER_SMEM>>>(hA, eps, 1, B1[1], B2[1], hB, gid, out);
    k_layer<<<grid, 256, LAYER_SMEM>>>(hB, eps, 2, B1[2], B2[2], nullptr, gid, out);
}